// round 4
// baseline (speedup 1.0000x reference)
#include <cuda_runtime.h>
#include <math.h>

#define NB 2
#define SN 512
#define DIM 256
#define NH 8
#define HD 32
#define QSCALE 0.17677669529663689f   // 1/sqrt(32)
#define FREQC  0.5756462732485115f    // ln(10000)/16
#define RSTR   769                     // smem row stride (odd -> conflict-free columns)

// ---------------- scratch (device globals) ----------------
__device__ float g_dist [NB*SN*SN];
__device__ float g_nodes[NB*SN*DIM];
__device__ float g_mu   [NB*SN];
__device__ float g_rs   [NB*SN];
__device__ float g_qkv  [NB*SN*3*DIM];   // [tok][768] : q | k | v
__device__ float g_q    [NB*NH*SN*HD];   // [bh][i][d] rotary, *SCALE
__device__ float g_kt   [NB*NH*HD*SN];   // [bh][d][i] rotary
__device__ float g_v    [NB*NH*SN*HD];   // [bh][i][d]
__device__ float g_qwe  [NB*NH*SN];
__device__ float g_qbe  [NB*NH*SN];
__device__ float g_attno[NB*SN*DIM];
__device__ float g_out  [NB*SN*DIM];
__device__ float g_tab  [SN*32];         // [i][ cs(16) | sn(16) ]

// ---------------- helpers ----------------
__device__ __forceinline__ float warpSum(float v){
    #pragma unroll
    for(int o=16;o;o>>=1) v += __shfl_xor_sync(0xffffffffu, v, o);
    return v;
}
__device__ __forceinline__ float warpMax(float v){
    #pragma unroll
    for(int o=16;o;o>>=1) v = fmaxf(v, __shfl_xor_sync(0xffffffffu, v, o));
    return v;
}

// ---------------- rotary trig table ----------------
__global__ void __launch_bounds__(256) k_tab(float* __restrict__ tab){
    int idx = blockIdx.x*256 + threadIdx.x;   // < 8192 = 512*16
    int i = idx >> 4, fd = idx & 15;
    float fr = (float)i * expf(-(float)fd * FREQC);
    tab[i*32 + fd]      = cosf(fr);
    tab[i*32 + 16 + fd] = sinf(fr);
}

// ---------------- pairwise distances ----------------
__global__ void __launch_bounds__(256) k_dist(const float* __restrict__ x, float* __restrict__ dist){
    int idx = blockIdx.x*256 + threadIdx.x;
    int j = idx & 511; int rest = idx >> 9;
    int i = rest & 511; int b = rest >> 9;
    const float* xi = x + (b*SN + i)*3;
    const float* xj = x + (b*SN + j)*3;
    float d0 = xi[0]-xj[0], d1 = xi[1]-xj[1], d2 = xi[2]-xj[2];
    float q = d0*d0 + d1*d1 + d2*d2;
    dist[idx] = (q > 0.f) ? sqrtf(q) : 0.f;
}

// ---------------- encoder + LN stats (block per token) ----------------
__global__ void __launch_bounds__(256) k_encode(const float* __restrict__ x, const float* __restrict__ t,
                                                const float* __restrict__ W, float* __restrict__ nodes,
                                                float* __restrict__ mu, float* __restrict__ rs){
    int tok = blockIdx.x; int tid = threadIdx.x;
    const float* xp = x + tok*3;
    float v = xp[0]*W[tid] + xp[1]*W[256+tid] + xp[2]*W[512+tid] + t[tok]*W[768+tid];
    nodes[tok*DIM + tid] = v;

    __shared__ float sred[8]; __shared__ float sb;
    int w = tid>>5, lane = tid&31;
    float s = warpSum(v);
    if(lane==0) sred[w] = s;
    __syncthreads();
    if(tid < 32){ float t2 = (tid<8)? sred[tid] : 0.f; t2 = warpSum(t2); if(tid==0) sb = t2; }
    __syncthreads();
    float mean = sb * (1.f/DIM);
    float d = v - mean;
    float s2 = warpSum(d*d);
    __syncthreads();
    if(lane==0) sred[w] = s2;
    __syncthreads();
    if(tid < 32){ float t2 = (tid<8)? sred[tid] : 0.f; t2 = warpSum(t2); if(tid==0) sb = t2; }
    __syncthreads();
    if(tid==0){ mu[tok] = mean; rs[tok] = rsqrtf(sb*(1.f/DIM) + 1e-5f); }
}

// ============ fused LN + QKV GEMM: C[1024,768] = LN(nodes)@[Wq|Wkv]+bias ============
// BM=64, BN=64, BK=32, 256 threads, grid (12, 16)
__global__ void __launch_bounds__(256) k_qkv(const float* __restrict__ A,
                                             const float* __restrict__ mu, const float* __restrict__ rs,
                                             const float* __restrict__ lng, const float* __restrict__ lnb,
                                             const float* __restrict__ Wq, const float* __restrict__ bq,
                                             const float* __restrict__ Wkv, const float* __restrict__ bkv,
                                             float* __restrict__ C){
    constexpr int BM=64, BK=32, BN=64, K=256;
    __shared__ float As[2][BM][BK+1];
    __shared__ __align__(16) float Bs[2][BK][BN];
    int tx = threadIdx.x;
    int bcol = blockIdx.x*BN, brow = blockIdx.y*BM;

    const float* W; const float* bias; int ldb;
    if(bcol < 256){ W = Wq + bcol;        bias = bq + bcol;        ldb = 256; }
    else          { W = Wkv + (bcol-256); bias = bkv + (bcol-256); ldb = 512; }

    int am[2], ak[2];
    #pragma unroll
    for(int u=0;u<2;u++){ int f = tx + u*256; am[u]=f>>3; ak[u]=(f&7)*4; }
    int brd[2], bcd[2];
    #pragma unroll
    for(int u=0;u<2;u++){ int f = tx + u*256; brd[u]=f>>4; bcd[u]=(f&15)*4; }

    const float* Ab = A + brow*K;
    float muv[2], rsv[2];
    #pragma unroll
    for(int u=0;u<2;u++){ muv[u] = mu[brow+am[u]]; rsv[u] = rs[brow+am[u]]; }

    float4 ra[2], rb[2];
    #pragma unroll
    for(int u=0;u<2;u++){
        float4 v = *(const float4*)(Ab + am[u]*K + ak[u]);
        float4 g = *(const float4*)(lng + ak[u]);
        float4 b = *(const float4*)(lnb + ak[u]);
        ra[u].x = fmaf((v.x-muv[u])*rsv[u], g.x, b.x);
        ra[u].y = fmaf((v.y-muv[u])*rsv[u], g.y, b.y);
        ra[u].z = fmaf((v.z-muv[u])*rsv[u], g.z, b.z);
        ra[u].w = fmaf((v.w-muv[u])*rsv[u], g.w, b.w);
    }
    #pragma unroll
    for(int u=0;u<2;u++) rb[u] = *(const float4*)(W + brd[u]*ldb + bcd[u]);
    #pragma unroll
    for(int u=0;u<2;u++){
        As[0][am[u]][ak[u]+0]=ra[u].x; As[0][am[u]][ak[u]+1]=ra[u].y;
        As[0][am[u]][ak[u]+2]=ra[u].z; As[0][am[u]][ak[u]+3]=ra[u].w;
    }
    #pragma unroll
    for(int u=0;u<2;u++) *(float4*)&Bs[0][brd[u]][bcd[u]] = rb[u];
    __syncthreads();

    int tcc = (tx&15)*4;
    int trr = (tx>>4)*4;
    float acc[4][4];
    #pragma unroll
    for(int u=0;u<4;u++){ acc[u][0]=0.f; acc[u][1]=0.f; acc[u][2]=0.f; acc[u][3]=0.f; }

    const int NT = K/BK;   // 8
    for(int t=0;t<NT;t++){
        int buf = t&1;
        if(t+1<NT){
            int k0 = (t+1)*BK;
            #pragma unroll
            for(int u=0;u<2;u++){
                float4 v = *(const float4*)(Ab + am[u]*K + k0 + ak[u]);
                float4 g = *(const float4*)(lng + k0 + ak[u]);
                float4 b = *(const float4*)(lnb + k0 + ak[u]);
                ra[u].x = fmaf((v.x-muv[u])*rsv[u], g.x, b.x);
                ra[u].y = fmaf((v.y-muv[u])*rsv[u], g.y, b.y);
                ra[u].z = fmaf((v.z-muv[u])*rsv[u], g.z, b.z);
                ra[u].w = fmaf((v.w-muv[u])*rsv[u], g.w, b.w);
            }
            #pragma unroll
            for(int u=0;u<2;u++) rb[u] = *(const float4*)(W + (k0+brd[u])*ldb + bcd[u]);
        }
        #pragma unroll
        for(int kk=0;kk<BK;kk++){
            float4 b = *(const float4*)&Bs[buf][kk][tcc];
            float a[4];
            #pragma unroll
            for(int u=0;u<4;u++) a[u] = As[buf][trr+u][kk];
            #pragma unroll
            for(int u=0;u<4;u++){
                acc[u][0]=fmaf(a[u],b.x,acc[u][0]);
                acc[u][1]=fmaf(a[u],b.y,acc[u][1]);
                acc[u][2]=fmaf(a[u],b.z,acc[u][2]);
                acc[u][3]=fmaf(a[u],b.w,acc[u][3]);
            }
        }
        if(t+1<NT){
            int nb = buf^1;
            #pragma unroll
            for(int u=0;u<2;u++){
                As[nb][am[u]][ak[u]+0]=ra[u].x; As[nb][am[u]][ak[u]+1]=ra[u].y;
                As[nb][am[u]][ak[u]+2]=ra[u].z; As[nb][am[u]][ak[u]+3]=ra[u].w;
            }
            #pragma unroll
            for(int u=0;u<2;u++) *(float4*)&Bs[nb][brd[u]][bcd[u]] = rb[u];
            __syncthreads();
        }
    }
    #pragma unroll
    for(int u=0;u<4;u++){
        #pragma unroll
        for(int vv=0;vv<4;vv++){
            int lc = tcc + vv;
            C[(brow+trr+u)*768 + bcol + lc] = acc[u][vv] + bias[lc];
        }
    }
}

// ============ plain SGEMM (O projection): BM=32, BN=64, BK=32, grid (4,32) ============
__global__ void __launch_bounds__(256) k_gemmO(const float* __restrict__ A, const float* __restrict__ W,
                                               const float* __restrict__ bias, float* __restrict__ C){
    constexpr int BM=32, BK=32, BN=64, K=256, Nc=256;
    __shared__ float As[2][BM][BK+1];
    __shared__ __align__(16) float Bs[2][BK][BN];
    int tx = threadIdx.x;
    int bcol = blockIdx.x*BN, brow = blockIdx.y*BM;

    int am = tx>>3, ak = (tx&7)*4;
    int brd[2], bcd[2];
    #pragma unroll
    for(int u=0;u<2;u++){ int f = tx + u*256; brd[u]=f>>4; bcd[u]=(f&15)*4; }

    const float* Ab = A + brow*K;
    const float* Wb = W + bcol;

    float4 ra, rb[2];
    ra = *(const float4*)(Ab + am*K + ak);
    #pragma unroll
    for(int u=0;u<2;u++) rb[u] = *(const float4*)(Wb + brd[u]*Nc + bcd[u]);
    As[0][am][ak+0]=ra.x; As[0][am][ak+1]=ra.y; As[0][am][ak+2]=ra.z; As[0][am][ak+3]=ra.w;
    #pragma unroll
    for(int u=0;u<2;u++) *(float4*)&Bs[0][brd[u]][bcd[u]] = rb[u];
    __syncthreads();

    int tcc = (tx&15)*4;
    int trr = (tx>>4)*2;
    float acc[2][4];
    #pragma unroll
    for(int u=0;u<2;u++){ acc[u][0]=0.f; acc[u][1]=0.f; acc[u][2]=0.f; acc[u][3]=0.f; }

    const int NT = K/BK;
    for(int t=0;t<NT;t++){
        int buf = t&1;
        if(t+1<NT){
            int k0 = (t+1)*BK;
            ra = *(const float4*)(Ab + am*K + k0 + ak);
            #pragma unroll
            for(int u=0;u<2;u++) rb[u] = *(const float4*)(Wb + (k0+brd[u])*Nc + bcd[u]);
        }
        #pragma unroll
        for(int kk=0;kk<BK;kk++){
            float4 b = *(const float4*)&Bs[buf][kk][tcc];
            float a0 = As[buf][trr  ][kk];
            float a1 = As[buf][trr+1][kk];
            acc[0][0]=fmaf(a0,b.x,acc[0][0]); acc[0][1]=fmaf(a0,b.y,acc[0][1]);
            acc[0][2]=fmaf(a0,b.z,acc[0][2]); acc[0][3]=fmaf(a0,b.w,acc[0][3]);
            acc[1][0]=fmaf(a1,b.x,acc[1][0]); acc[1][1]=fmaf(a1,b.y,acc[1][1]);
            acc[1][2]=fmaf(a1,b.z,acc[1][2]); acc[1][3]=fmaf(a1,b.w,acc[1][3]);
        }
        if(t+1<NT){
            int nb = buf^1;
            As[nb][am][ak+0]=ra.x; As[nb][am][ak+1]=ra.y; As[nb][am][ak+2]=ra.z; As[nb][am][ak+3]=ra.w;
            #pragma unroll
            for(int u=0;u<2;u++) *(float4*)&Bs[nb][brd[u]][bcd[u]] = rb[u];
            __syncthreads();
        }
    }
    #pragma unroll
    for(int u=0;u<2;u++){
        #pragma unroll
        for(int vv=0;vv<4;vv++){
            int col = bcol + tcc + vv;
            C[(brow+trr+u)*Nc + col] = acc[u][vv] + bias[col];
        }
    }
}

// ---------------- rotary: smem-staged, coalesced kt transpose ----------------
// grid: NB*16 blocks (32 tokens each), 256 threads, dynamic smem 32*RSTR*4 bytes
__global__ void __launch_bounds__(256) k_rot(const float* __restrict__ qkv,
                                             const float* __restrict__ We, const float* __restrict__ be,
                                             const float* __restrict__ tab,
                                             float* __restrict__ q, float* __restrict__ qwe, float* __restrict__ qbe,
                                             float* __restrict__ kt, float* __restrict__ v){
    extern __shared__ float sbuf[];      // [32][RSTR]
    int blk = blockIdx.x;
    int b = blk >> 4, i0 = (blk & 15)*32;
    int tx = threadIdx.x;

    // phase A: stage raw qkv rows (coalesced gmem reads)
    const float4* src = (const float4*)(qkv + (b*SN + i0)*768);
    for(int p = tx; p < 32*192; p += 256){     // 768/4 = 192 float4 per row
        float4 vv = src[p];
        int tok = p/192, c = (p%192)*4;
        float* row = sbuf + tok*RSTR + c;
        row[0]=vv.x; row[1]=vv.y; row[2]=vv.z; row[3]=vv.w;
    }
    __syncthreads();

    // phase B: q rotary + qwe/qbe + v relayout; thread = (tok, h)
    {
        int tok = tx>>3, h = tx&7;
        int i = i0 + tok, bh = b*NH + h;
        const float* row = sbuf + tok*RSTR;
        float cs[16], sn[16];
        #pragma unroll
        for(int u=0;u<4;u++){
            float4 c4 = *(const float4*)(tab + i*32 + u*4);
            float4 s4 = *(const float4*)(tab + i*32 + 16 + u*4);
            cs[u*4+0]=c4.x; cs[u*4+1]=c4.y; cs[u*4+2]=c4.z; cs[u*4+3]=c4.w;
            sn[u*4+0]=s4.x; sn[u*4+1]=s4.y; sn[u*4+2]=s4.z; sn[u*4+3]=s4.w;
        }
        float qv[32];
        #pragma unroll
        for(int d=0;d<32;d++){ int dd = (d + h*4)&31; qv[dd] = row[h*32 + dd]; }
        float dwe = 0.f, dbe = 0.f;
        float qo[32];
        #pragma unroll
        for(int d=0;d<32;d++){
            int fd = d & 15;
            float rot = (d<16) ? -qv[d+16] : qv[d-16];
            float val = (qv[d]*cs[fd] + rot*sn[fd]) * QSCALE;
            qo[d] = val;
            dwe = fmaf(val, We[h*32+d], dwe);
            dbe = fmaf(val, be[h*32+d], dbe);
        }
        float* qdst = q + (bh*SN + i)*HD;
        #pragma unroll
        for(int d=0;d<32;d+=4) *(float4*)(qdst+d) = make_float4(qo[d],qo[d+1],qo[d+2],qo[d+3]);
        qwe[bh*SN+i] = dwe; qbe[bh*SN+i] = dbe;

        float* vdst = v + (bh*SN + i)*HD;
        #pragma unroll
        for(int d=0;d<32;d+=4){
            int base = 512 + h*32 + ((d + h*4)&28);   // staggered by 4s
            int dd = (d + h*4)&28;
            *(float4*)(vdst+dd) = make_float4(row[base],row[base+1],row[base+2],row[base+3]);
        }
    }

    // phase C: k rotary, transposed store (lane = token -> coalesced kt writes)
    {
        int h = tx>>5, lane = tx&31;
        int i = i0 + lane, bh = b*NH + h;
        float cs[16], sn[16];
        #pragma unroll
        for(int u=0;u<4;u++){
            float4 c4 = *(const float4*)(tab + i*32 + u*4);
            float4 s4 = *(const float4*)(tab + i*32 + 16 + u*4);
            cs[u*4+0]=c4.x; cs[u*4+1]=c4.y; cs[u*4+2]=c4.z; cs[u*4+3]=c4.w;
            sn[u*4+0]=s4.x; sn[u*4+1]=s4.y; sn[u*4+2]=s4.z; sn[u*4+3]=s4.w;
        }
        float kv[32];
        #pragma unroll
        for(int d=0;d<32;d++) kv[d] = sbuf[lane*RSTR + 256 + h*32 + d];  // conflict-free (odd stride)
        #pragma unroll
        for(int d=0;d<32;d++){
            int fd = d & 15;
            float rot = (d<16) ? -kv[d+16] : kv[d-16];
            kt[(bh*HD + d)*SN + i] = kv[d]*cs[fd] + rot*sn[fd];
        }
    }
}

// ---------------- attention: warp handles 2 query rows ----------------
__global__ void __launch_bounds__(256) k_attn2(
    const float* __restrict__ q, const float* __restrict__ kt, const float* __restrict__ v,
    const float* __restrict__ qwe, const float* __restrict__ qbe, const float* __restrict__ dist,
    const float* __restrict__ We, const float* __restrict__ be, float* __restrict__ out)
{
    __shared__ __align__(16) float sp[16][512];
    int w = threadIdx.x >> 5, lane = threadIdx.x & 31;
    int bh = blockIdx.x >> 5;
    int chunk = blockIdx.x & 31;
    int b = bh >> 3, h = bh & 7;
    int i0 = chunk*16 + w*2, i1 = i0 + 1;

    float qr0[32], qr1[32];
    {
        float qv0 = q[(bh*SN + i0)*HD + lane];
        float qv1 = q[(bh*SN + i1)*HD + lane];
        #pragma unroll
        for(int d=0;d<32;d++){ qr0[d] = __shfl_sync(0xffffffffu, qv0, d);
                               qr1[d] = __shfl_sync(0xffffffffu, qv1, d); }
    }
    float cwe0 = qwe[bh*SN + i0], cwe1 = qwe[bh*SN + i1];
    float cbe0 = qbe[bh*SN + i0], cbe1 = qbe[bh*SN + i1];
    const float* Kt = kt + bh*HD*SN;
    const float* D0 = dist + (b*SN + i0)*SN;
    const float* D1 = dist + (b*SN + i1)*SN;

    float m0 = -1e30f, m1 = -1e30f;
    #pragma unroll
    for(int cb=0;cb<4;cb++){
        int j0 = cb*128 + lane*4;
        float4 s0 = make_float4(cbe0,cbe0,cbe0,cbe0);
        float4 s1 = make_float4(cbe1,cbe1,cbe1,cbe1);
        #pragma unroll
        for(int d=0;d<32;d++){
            float4 kk = *(const float4*)(Kt + d*SN + j0);
            s0.x = fmaf(qr0[d], kk.x, s0.x); s0.y = fmaf(qr0[d], kk.y, s0.y);
            s0.z = fmaf(qr0[d], kk.z, s0.z); s0.w = fmaf(qr0[d], kk.w, s0.w);
            s1.x = fmaf(qr1[d], kk.x, s1.x); s1.y = fmaf(qr1[d], kk.y, s1.y);
            s1.z = fmaf(qr1[d], kk.z, s1.z); s1.w = fmaf(qr1[d], kk.w, s1.w);
        }
        float4 d0 = *(const float4*)(D0 + j0);
        float4 d1 = *(const float4*)(D1 + j0);
        s0.x = fmaf(d0.x, cwe0, s0.x); s0.y = fmaf(d0.y, cwe0, s0.y);
        s0.z = fmaf(d0.z, cwe0, s0.z); s0.w = fmaf(d0.w, cwe0, s0.w);
        s1.x = fmaf(d1.x, cwe1, s1.x); s1.y = fmaf(d1.y, cwe1, s1.y);
        s1.z = fmaf(d1.z, cwe1, s1.z); s1.w = fmaf(d1.w, cwe1, s1.w);
        *(float4*)&sp[w*2  ][j0] = s0;
        *(float4*)&sp[w*2+1][j0] = s1;
        m0 = fmaxf(m0, fmaxf(fmaxf(s0.x,s0.y), fmaxf(s0.z,s0.w)));
        m1 = fmaxf(m1, fmaxf(fmaxf(s1.x,s1.y), fmaxf(s1.z,s1.w)));
    }
    m0 = warpMax(m0); m1 = warpMax(m1);

    float sum0 = 0.f, sum1 = 0.f, sd0 = 0.f, sd1 = 0.f;
    #pragma unroll
    for(int cb=0;cb<4;cb++){
        int j0 = cb*128 + lane*4;
        float4 s0 = *(const float4*)&sp[w*2  ][j0];
        float4 s1 = *(const float4*)&sp[w*2+1][j0];
        float4 d0 = *(const float4*)(D0 + j0);
        float4 d1 = *(const float4*)(D1 + j0);
        float4 p0, p1;
        p0.x = __expf(s0.x-m0); p0.y = __expf(s0.y-m0); p0.z = __expf(s0.z-m0); p0.w = __expf(s0.w-m0);
        p1.x = __expf(s1.x-m1); p1.y = __expf(s1.y-m1); p1.z = __expf(s1.z-m1); p1.w = __expf(s1.w-m1);
        sum0 += (p0.x+p0.y)+(p0.z+p0.w);
        sum1 += (p1.x+p1.y)+(p1.z+p1.w);
        sd0 = fmaf(p0.x,d0.x,sd0); sd0 = fmaf(p0.y,d0.y,sd0); sd0 = fmaf(p0.z,d0.z,sd0); sd0 = fmaf(p0.w,d0.w,sd0);
        sd1 = fmaf(p1.x,d1.x,sd1); sd1 = fmaf(p1.y,d1.y,sd1); sd1 = fmaf(p1.z,d1.z,sd1); sd1 = fmaf(p1.w,d1.w,sd1);
        *(float4*)&sp[w*2  ][j0] = p0;
        *(float4*)&sp[w*2+1][j0] = p1;
    }
    sum0 = warpSum(sum0); sum1 = warpSum(sum1);
    sd0  = warpSum(sd0);  sd1  = warpSum(sd1);
    float inv0 = 1.f/sum0, inv1 = 1.f/sum1;
    __syncwarp();

    const float* Vp = v + bh*SN*HD;
    const float4* p0v = (const float4*)sp[w*2];
    const float4* p1v = (const float4*)sp[w*2+1];
    float a00=0.f,a01=0.f,a02=0.f,a03=0.f;
    float a10=0.f,a11=0.f,a12=0.f,a13=0.f;
    #pragma unroll 4
    for(int j4=0;j4<128;j4++){
        float4 p0 = p0v[j4];
        float4 p1 = p1v[j4];
        const float* vb = Vp + j4*128 + lane;
        float v0 = vb[0], v1 = vb[32], v2 = vb[64], v3 = vb[96];
        a00 = fmaf(p0.x,v0,a00); a01 = fmaf(p0.y,v1,a01);
        a02 = fmaf(p0.z,v2,a02); a03 = fmaf(p0.w,v3,a03);
        a10 = fmaf(p1.x,v0,a10); a11 = fmaf(p1.y,v1,a11);
        a12 = fmaf(p1.z,v2,a12); a13 = fmaf(p1.w,v3,a13);
    }
    float a0 = (a00+a01)+(a02+a03);
    float a1 = (a10+a11)+(a12+a13);
    float wl = We[h*32 + lane], bl = be[h*32 + lane];
    out[((b*SN + i0)*NH + h)*HD + lane] = a0*inv0 + (sd0*inv0)*wl + bl;
    out[((b*SN + i1)*NH + h)*HD + lane] = a1*inv1 + (sd1*inv1)*wl + bl;
}

// ---------------- fused gate + residual + next-layer LN stats ----------------
__global__ void __launch_bounds__(256) k_gate(const float* __restrict__ o, const float* __restrict__ wg,
                                              float* __restrict__ nodes,
                                              float* __restrict__ mu, float* __restrict__ rs){
    int w = threadIdx.x >> 5, lane = threadIdx.x & 31;
    int tok = blockIdx.x*8 + w;
    const float* op = o + tok*DIM;
    float* np = nodes + tok*DIM;
    float ov[8], nv[8];
    float s = 0.f;
    #pragma unroll
    for(int k=0;k<8;k++){
        int c = lane + k*32;
        ov[k] = op[c]; nv[k] = np[c];
        s = fmaf(ov[k], wg[c] + wg[512+c], s);
        s = fmaf(nv[k], wg[256+c] - wg[512+c], s);
    }
    s = warpSum(s);
    float g = 1.f / (1.f + __expf(-s));
    float vs = 0.f;
    float newv[8];
    #pragma unroll
    for(int k=0;k<8;k++){
        newv[k] = ov[k]*g + nv[k]*(1.f - g);
        vs += newv[k];
    }
    vs = warpSum(vs);
    float mean = vs * (1.f/DIM);
    float v2 = 0.f;
    #pragma unroll
    for(int k=0;k<8;k++){
        int c = lane + k*32;
        np[c] = newv[k];
        float d = newv[k] - mean;
        v2 = fmaf(d, d, v2);
    }
    v2 = warpSum(v2);
    if(lane == 0){ mu[tok] = mean; rs[tok] = rsqrtf(v2*(1.f/DIM) + 1e-5f); }
}

// ---------------- decoder ----------------
__global__ void __launch_bounds__(256) k_decode(const float* __restrict__ nodes, const float* __restrict__ Wd,
                                                float* __restrict__ out){
    int w = threadIdx.x >> 5, lane = threadIdx.x & 31;
    int tok = blockIdx.x*8 + w;
    const float* np = nodes + tok*DIM;
    float a0 = 0.f, a1 = 0.f, a2 = 0.f;
    #pragma unroll
    for(int k0=0;k0<8;k0++){
        int k = lane + k0*32;
        float nv = np[k];
        a0 = fmaf(nv, Wd[k*3+0], a0);
        a1 = fmaf(nv, Wd[k*3+1], a1);
        a2 = fmaf(nv, Wd[k*3+2], a2);
    }
    a0 = warpSum(a0); a1 = warpSum(a1); a2 = warpSum(a2);
    if(lane == 0){
        out[tok*3+0] = a0; out[tok*3+1] = a1; out[tok*3+2] = a2;
    }
}

// ---------------- launch ----------------
extern "C" void kernel_launch(void* const* d_in, const int* in_sizes, int n_in,
                              void* d_out, int out_size){
    (void)in_sizes; (void)n_in; (void)out_size;
    const float* x     = (const float*)d_in[0];
    const float* t     = (const float*)d_in[1];
    const float* W_enc = (const float*)d_in[2];
    const float* W_dec = (const float*)d_in[3];
    const float* ln_g  = (const float*)d_in[4];
    const float* ln_b  = (const float*)d_in[5];
    const float* Wq    = (const float*)d_in[6];
    const float* bq    = (const float*)d_in[7];
    const float* Wkv   = (const float*)d_in[8];
    const float* bkv   = (const float*)d_in[9];
    const float* We    = (const float*)d_in[10];
    const float* be    = (const float*)d_in[11];
    const float* Wo    = (const float*)d_in[12];
    const float* bo    = (const float*)d_in[13];
    const float* Wg    = (const float*)d_in[14];
    float* out = (float*)d_out;

    float *dist,*nodes,*mu,*rs,*qkv,*q,*kt,*v,*qwe,*qbe,*attno,*ofull,*tab;
    cudaGetSymbolAddress((void**)&dist,  g_dist);
    cudaGetSymbolAddress((void**)&nodes, g_nodes);
    cudaGetSymbolAddress((void**)&mu,    g_mu);
    cudaGetSymbolAddress((void**)&rs,    g_rs);
    cudaGetSymbolAddress((void**)&qkv,   g_qkv);
    cudaGetSymbolAddress((void**)&q,     g_q);
    cudaGetSymbolAddress((void**)&kt,    g_kt);
    cudaGetSymbolAddress((void**)&v,     g_v);
    cudaGetSymbolAddress((void**)&qwe,   g_qwe);
    cudaGetSymbolAddress((void**)&qbe,   g_qbe);
    cudaGetSymbolAddress((void**)&attno, g_attno);
    cudaGetSymbolAddress((void**)&ofull, g_out);
    cudaGetSymbolAddress((void**)&tab,   g_tab);

    const int rot_smem = 32*RSTR*4;     // 98432 bytes
    cudaFuncSetAttribute(k_rot, cudaFuncAttributeMaxDynamicSharedMemorySize, rot_smem);

    k_tab   <<<32,256>>>(tab);
    k_dist  <<<2048,256>>>(x, dist);
    k_encode<<<1024,256>>>(x, t, W_enc, nodes, mu, rs);

    for(int l=0;l<2;l++){
        k_qkv<<<dim3(12,16),256>>>(nodes, mu, rs, ln_g + l*DIM, ln_b + l*DIM,
                                   Wq + l*DIM*DIM, bq + l*DIM,
                                   Wkv + l*DIM*2*DIM, bkv + l*2*DIM, qkv);
        k_rot<<<32,256,rot_smem>>>(qkv, We + l*DIM, be + l*DIM, tab, q, qwe, qbe, kt, v);
        k_attn2<<<512,256>>>(q, kt, v, qwe, qbe, dist, We + l*DIM, be + l*DIM, attno);
        k_gemmO<<<dim3(4,32),256>>>(attno, Wo + l*DIM*DIM, bo + l*DIM, ofull);
        k_gate<<<128,256>>>(ofull, Wg + l*3*DIM, nodes, mu, rs);
    }
    k_decode<<<128,256>>>(nodes, W_dec, out);
}

// round 5
// speedup vs baseline: 1.0444x; 1.0444x over previous
#include <cuda_runtime.h>
#include <math.h>

#define NB 2
#define SN 512
#define DIM 256
#define NH 8
#define HD 32
#define QSCALE 0.17677669529663689f   // 1/sqrt(32)
#define FREQC  0.5756462732485115f    // ln(10000)/16

// ---------------- scratch (device globals) ----------------
__device__ float g_dist [NB*SN*SN];
__device__ float g_nodes[NB*SN*DIM];
__device__ float g_mu   [NB*SN];
__device__ float g_rs   [NB*SN];
__device__ float g_qkv  [NB*SN*3*DIM];   // [tok][768] : q | k | v
__device__ float g_q    [NB*NH*SN*HD];   // [bh][i][d] rotary, *SCALE
__device__ float g_kt   [NB*NH*HD*SN];   // [bh][d][i] rotary
__device__ float g_v    [NB*NH*SN*HD];   // [bh][i][d]
__device__ float g_qwe  [NB*NH*SN];
__device__ float g_qbe  [NB*NH*SN];
__device__ float g_attno[NB*SN*DIM];
__device__ float g_out  [NB*SN*DIM];
__device__ float g_tab  [SN*32];         // [i][ cs(16) | sn(16) ]

// ---------------- helpers ----------------
__device__ __forceinline__ float warpSum(float v){
    #pragma unroll
    for(int o=16;o;o>>=1) v += __shfl_xor_sync(0xffffffffu, v, o);
    return v;
}
__device__ __forceinline__ float warpMax(float v){
    #pragma unroll
    for(int o=16;o;o>>=1) v = fmaxf(v, __shfl_xor_sync(0xffffffffu, v, o));
    return v;
}

// ---------------- rotary trig table ----------------
__global__ void __launch_bounds__(256) k_tab(float* __restrict__ tab){
    int idx = blockIdx.x*256 + threadIdx.x;   // < 8192 = 512*16
    int i = idx >> 4, fd = idx & 15;
    float fr = (float)i * expf(-(float)fd * FREQC);
    tab[i*32 + fd]      = cosf(fr);
    tab[i*32 + 16 + fd] = sinf(fr);
}

// ---------------- pairwise distances ----------------
__global__ void __launch_bounds__(256) k_dist(const float* __restrict__ x, float* __restrict__ dist){
    int idx = blockIdx.x*256 + threadIdx.x;
    int j = idx & 511; int rest = idx >> 9;
    int i = rest & 511; int b = rest >> 9;
    const float* xi = x + (b*SN + i)*3;
    const float* xj = x + (b*SN + j)*3;
    float d0 = xi[0]-xj[0], d1 = xi[1]-xj[1], d2 = xi[2]-xj[2];
    float q = d0*d0 + d1*d1 + d2*d2;
    dist[idx] = (q > 0.f) ? sqrtf(q) : 0.f;
}

// ---------------- encoder + LN stats (block per token) ----------------
__global__ void __launch_bounds__(256) k_encode(const float* __restrict__ x, const float* __restrict__ t,
                                                const float* __restrict__ W, float* __restrict__ nodes,
                                                float* __restrict__ mu, float* __restrict__ rs){
    int tok = blockIdx.x; int tid = threadIdx.x;
    const float* xp = x + tok*3;
    float v = xp[0]*W[tid] + xp[1]*W[256+tid] + xp[2]*W[512+tid] + t[tok]*W[768+tid];
    nodes[tok*DIM + tid] = v;

    __shared__ float sred[8]; __shared__ float sb;
    int w = tid>>5, lane = tid&31;
    float s = warpSum(v);
    if(lane==0) sred[w] = s;
    __syncthreads();
    if(tid < 32){ float t2 = (tid<8)? sred[tid] : 0.f; t2 = warpSum(t2); if(tid==0) sb = t2; }
    __syncthreads();
    float mean = sb * (1.f/DIM);
    float d = v - mean;
    float s2 = warpSum(d*d);
    __syncthreads();
    if(lane==0) sred[w] = s2;
    __syncthreads();
    if(tid < 32){ float t2 = (tid<8)? sred[tid] : 0.f; t2 = warpSum(t2); if(tid==0) sb = t2; }
    __syncthreads();
    if(tid==0){ mu[tok] = mean; rs[tok] = rsqrtf(sb*(1.f/DIM) + 1e-5f); }
}

// ============ fused LN + QKV GEMM, low-smem: BM=64, BN=64, BK=16, grid (12,16) ============
__global__ void __launch_bounds__(256) k_qkv(const float* __restrict__ A,
                                             const float* __restrict__ mu, const float* __restrict__ rs,
                                             const float* __restrict__ lng, const float* __restrict__ lnb,
                                             const float* __restrict__ Wq, const float* __restrict__ bq,
                                             const float* __restrict__ Wkv, const float* __restrict__ bkv,
                                             float* __restrict__ C){
    constexpr int BM=64, BK=16, BN=64, K=256;
    __shared__ __align__(16) float As[2][BK][BM+4];   // k-major
    __shared__ __align__(16) float Bs[2][BK][BN];
    int tx = threadIdx.x;
    int bcol = blockIdx.x*BN, brow = blockIdx.y*BM;

    const float* W; const float* bias; int ldb;
    if(bcol < 256){ W = Wq + bcol;        bias = bq + bcol;        ldb = 256; }
    else          { W = Wkv + (bcol-256); bias = bkv + (bcol-256); ldb = 512; }

    int am = tx>>2, ak = (tx&3)*4;          // A: 64 rows x 16 k, 1 float4/thread
    int brd = tx>>4, bcd = (tx&15)*4;       // B: 16 k x 64 cols, 1 float4/thread

    const float* Ab = A + brow*K;
    float muv = mu[brow+am], rsv = rs[brow+am];

    float4 ra, rb;
    {
        float4 v = *(const float4*)(Ab + am*K + ak);
        float4 g = *(const float4*)(lng + ak);
        float4 b = *(const float4*)(lnb + ak);
        ra.x = fmaf((v.x-muv)*rsv, g.x, b.x);
        ra.y = fmaf((v.y-muv)*rsv, g.y, b.y);
        ra.z = fmaf((v.z-muv)*rsv, g.z, b.z);
        ra.w = fmaf((v.w-muv)*rsv, g.w, b.w);
    }
    rb = *(const float4*)(W + brd*ldb + bcd);
    As[0][ak+0][am]=ra.x; As[0][ak+1][am]=ra.y; As[0][ak+2][am]=ra.z; As[0][ak+3][am]=ra.w;
    *(float4*)&Bs[0][brd][bcd] = rb;
    __syncthreads();

    int tcc = (tx&15)*4;
    int trr = (tx>>4)*4;
    float acc[4][4];
    #pragma unroll
    for(int u=0;u<4;u++){ acc[u][0]=0.f; acc[u][1]=0.f; acc[u][2]=0.f; acc[u][3]=0.f; }

    const int NT = K/BK;   // 16
    for(int t=0;t<NT;t++){
        int buf = t&1;
        if(t+1<NT){
            int k0 = (t+1)*BK;
            float4 v = *(const float4*)(Ab + am*K + k0 + ak);
            float4 g = *(const float4*)(lng + k0 + ak);
            float4 b = *(const float4*)(lnb + k0 + ak);
            ra.x = fmaf((v.x-muv)*rsv, g.x, b.x);
            ra.y = fmaf((v.y-muv)*rsv, g.y, b.y);
            ra.z = fmaf((v.z-muv)*rsv, g.z, b.z);
            ra.w = fmaf((v.w-muv)*rsv, g.w, b.w);
            rb = *(const float4*)(W + (k0+brd)*ldb + bcd);
        }
        #pragma unroll
        for(int kk=0;kk<BK;kk++){
            float4 a = *(const float4*)&As[buf][kk][trr];
            float4 b = *(const float4*)&Bs[buf][kk][tcc];
            acc[0][0]=fmaf(a.x,b.x,acc[0][0]); acc[0][1]=fmaf(a.x,b.y,acc[0][1]);
            acc[0][2]=fmaf(a.x,b.z,acc[0][2]); acc[0][3]=fmaf(a.x,b.w,acc[0][3]);
            acc[1][0]=fmaf(a.y,b.x,acc[1][0]); acc[1][1]=fmaf(a.y,b.y,acc[1][1]);
            acc[1][2]=fmaf(a.y,b.z,acc[1][2]); acc[1][3]=fmaf(a.y,b.w,acc[1][3]);
            acc[2][0]=fmaf(a.z,b.x,acc[2][0]); acc[2][1]=fmaf(a.z,b.y,acc[2][1]);
            acc[2][2]=fmaf(a.z,b.z,acc[2][2]); acc[2][3]=fmaf(a.z,b.w,acc[2][3]);
            acc[3][0]=fmaf(a.w,b.x,acc[3][0]); acc[3][1]=fmaf(a.w,b.y,acc[3][1]);
            acc[3][2]=fmaf(a.w,b.z,acc[3][2]); acc[3][3]=fmaf(a.w,b.w,acc[3][3]);
        }
        if(t+1<NT){
            int nb = buf^1;
            As[nb][ak+0][am]=ra.x; As[nb][ak+1][am]=ra.y;
            As[nb][ak+2][am]=ra.z; As[nb][ak+3][am]=ra.w;
            *(float4*)&Bs[nb][brd][bcd] = rb;
            __syncthreads();
        }
    }
    #pragma unroll
    for(int u=0;u<4;u++){
        #pragma unroll
        for(int vv=0;vv<4;vv++){
            int lc = tcc + vv;
            C[(brow+trr+u)*768 + bcol + lc] = acc[u][vv] + bias[lc];
        }
    }
}

// ============ O projection GEMM, low-smem: BM=32, BN=64, BK=16, grid (4,32) ============
__global__ void __launch_bounds__(256) k_gemmO(const float* __restrict__ A, const float* __restrict__ W,
                                               const float* __restrict__ bias, float* __restrict__ C){
    constexpr int BM=32, BK=16, BN=64, K=256, Nc=256;
    __shared__ __align__(16) float As[2][BK][BM+4];
    __shared__ __align__(16) float Bs[2][BK][BN];
    int tx = threadIdx.x;
    int bcol = blockIdx.x*BN, brow = blockIdx.y*BM;

    int am = tx>>2, ak = (tx&3)*4;          // only tx<128 load A
    int brd = tx>>4, bcd = (tx&15)*4;

    const float* Ab = A + brow*K;
    const float* Wb = W + bcol;

    float4 ra = make_float4(0.f,0.f,0.f,0.f), rb;
    if(tx < 128) ra = *(const float4*)(Ab + am*K + ak);
    rb = *(const float4*)(Wb + brd*Nc + bcd);
    if(tx < 128){
        As[0][ak+0][am]=ra.x; As[0][ak+1][am]=ra.y; As[0][ak+2][am]=ra.z; As[0][ak+3][am]=ra.w;
    }
    *(float4*)&Bs[0][brd][bcd] = rb;
    __syncthreads();

    int tcc = (tx&15)*4;
    int trr = (tx>>4)*2;
    float acc[2][4];
    #pragma unroll
    for(int u=0;u<2;u++){ acc[u][0]=0.f; acc[u][1]=0.f; acc[u][2]=0.f; acc[u][3]=0.f; }

    const int NT = K/BK;   // 16
    for(int t=0;t<NT;t++){
        int buf = t&1;
        if(t+1<NT){
            int k0 = (t+1)*BK;
            if(tx < 128) ra = *(const float4*)(Ab + am*K + k0 + ak);
            rb = *(const float4*)(Wb + (k0+brd)*Nc + bcd);
        }
        #pragma unroll
        for(int kk=0;kk<BK;kk++){
            float2 a = *(const float2*)&As[buf][kk][trr];
            float4 b = *(const float4*)&Bs[buf][kk][tcc];
            acc[0][0]=fmaf(a.x,b.x,acc[0][0]); acc[0][1]=fmaf(a.x,b.y,acc[0][1]);
            acc[0][2]=fmaf(a.x,b.z,acc[0][2]); acc[0][3]=fmaf(a.x,b.w,acc[0][3]);
            acc[1][0]=fmaf(a.y,b.x,acc[1][0]); acc[1][1]=fmaf(a.y,b.y,acc[1][1]);
            acc[1][2]=fmaf(a.y,b.z,acc[1][2]); acc[1][3]=fmaf(a.y,b.w,acc[1][3]);
        }
        if(t+1<NT){
            int nb = buf^1;
            if(tx < 128){
                As[nb][ak+0][am]=ra.x; As[nb][ak+1][am]=ra.y;
                As[nb][ak+2][am]=ra.z; As[nb][ak+3][am]=ra.w;
            }
            *(float4*)&Bs[nb][brd][bcd] = rb;
            __syncthreads();
        }
    }
    #pragma unroll
    for(int u=0;u<2;u++){
        #pragma unroll
        for(int vv=0;vv<4;vv++){
            int col = bcol + tcc + vv;
            C[(brow+trr+u)*Nc + col] = acc[u][vv] + bias[col];
        }
    }
}

// ---------------- rotary Q/K (+ q.We, q.be) + V relayout (table trig) ----------------
__global__ void __launch_bounds__(256) k_rot(const float* __restrict__ qkv,
                                             const float* __restrict__ We, const float* __restrict__ be,
                                             const float* __restrict__ tab,
                                             float* __restrict__ q, float* __restrict__ qwe, float* __restrict__ qbe,
                                             float* __restrict__ kt, float* __restrict__ v){
    int bi = blockIdx.x;
    int b = bi >> 9, i = bi & 511;
    int h = threadIdx.x >> 5, d = threadIdx.x & 31;
    int bh = b*NH + h;
    const float* row = qkv + bi*768;
    int fd = d & 15;
    float cs = tab[i*32 + fd];
    float sn = tab[i*32 + 16 + fd];

    float qv = row[h*32 + d];
    float qo = row[h*32 + ((d+16)&31)];
    float qrot = (d < 16) ? -qo : qo;
    float qval = (qv*cs + qrot*sn) * QSCALE;
    q[(bh*SN + i)*HD + d] = qval;

    float kv = row[256 + h*32 + d];
    float ko = row[256 + h*32 + ((d+16)&31)];
    float krot = (d < 16) ? -ko : ko;
    kt[(bh*HD + d)*SN + i] = kv*cs + krot*sn;

    v[(bh*SN + i)*HD + d] = row[512 + h*32 + d];

    float dwe = warpSum(qval * We[h*32 + d]);
    float dbe = warpSum(qval * be[h*32 + d]);
    if(d == 0){ qwe[bh*SN + i] = dwe; qbe[bh*SN + i] = dbe; }
}

// ---------------- attention: warp handles 2 query rows ----------------
__global__ void __launch_bounds__(256) k_attn2(
    const float* __restrict__ q, const float* __restrict__ kt, const float* __restrict__ v,
    const float* __restrict__ qwe, const float* __restrict__ qbe, const float* __restrict__ dist,
    const float* __restrict__ We, const float* __restrict__ be, float* __restrict__ out)
{
    __shared__ __align__(16) float sp[16][512];
    int w = threadIdx.x >> 5, lane = threadIdx.x & 31;
    int bh = blockIdx.x >> 5;
    int chunk = blockIdx.x & 31;
    int b = bh >> 3, h = bh & 7;
    int i0 = chunk*16 + w*2, i1 = i0 + 1;

    float qr0[32], qr1[32];
    {
        float qv0 = q[(bh*SN + i0)*HD + lane];
        float qv1 = q[(bh*SN + i1)*HD + lane];
        #pragma unroll
        for(int d=0;d<32;d++){ qr0[d] = __shfl_sync(0xffffffffu, qv0, d);
                               qr1[d] = __shfl_sync(0xffffffffu, qv1, d); }
    }
    float cwe0 = qwe[bh*SN + i0], cwe1 = qwe[bh*SN + i1];
    float cbe0 = qbe[bh*SN + i0], cbe1 = qbe[bh*SN + i1];
    const float* Kt = kt + bh*HD*SN;
    const float* D0 = dist + (b*SN + i0)*SN;
    const float* D1 = dist + (b*SN + i1)*SN;

    float m0 = -1e30f, m1 = -1e30f;
    #pragma unroll
    for(int cb=0;cb<4;cb++){
        int j0 = cb*128 + lane*4;
        float4 s0 = make_float4(cbe0,cbe0,cbe0,cbe0);
        float4 s1 = make_float4(cbe1,cbe1,cbe1,cbe1);
        #pragma unroll
        for(int d=0;d<32;d++){
            float4 kk = *(const float4*)(Kt + d*SN + j0);
            s0.x = fmaf(qr0[d], kk.x, s0.x); s0.y = fmaf(qr0[d], kk.y, s0.y);
            s0.z = fmaf(qr0[d], kk.z, s0.z); s0.w = fmaf(qr0[d], kk.w, s0.w);
            s1.x = fmaf(qr1[d], kk.x, s1.x); s1.y = fmaf(qr1[d], kk.y, s1.y);
            s1.z = fmaf(qr1[d], kk.z, s1.z); s1.w = fmaf(qr1[d], kk.w, s1.w);
        }
        float4 d0 = *(const float4*)(D0 + j0);
        float4 d1 = *(const float4*)(D1 + j0);
        s0.x = fmaf(d0.x, cwe0, s0.x); s0.y = fmaf(d0.y, cwe0, s0.y);
        s0.z = fmaf(d0.z, cwe0, s0.z); s0.w = fmaf(d0.w, cwe0, s0.w);
        s1.x = fmaf(d1.x, cwe1, s1.x); s1.y = fmaf(d1.y, cwe1, s1.y);
        s1.z = fmaf(d1.z, cwe1, s1.z); s1.w = fmaf(d1.w, cwe1, s1.w);
        *(float4*)&sp[w*2  ][j0] = s0;
        *(float4*)&sp[w*2+1][j0] = s1;
        m0 = fmaxf(m0, fmaxf(fmaxf(s0.x,s0.y), fmaxf(s0.z,s0.w)));
        m1 = fmaxf(m1, fmaxf(fmaxf(s1.x,s1.y), fmaxf(s1.z,s1.w)));
    }
    m0 = warpMax(m0); m1 = warpMax(m1);

    float sum0 = 0.f, sum1 = 0.f, sd0 = 0.f, sd1 = 0.f;
    #pragma unroll
    for(int cb=0;cb<4;cb++){
        int j0 = cb*128 + lane*4;
        float4 s0 = *(const float4*)&sp[w*2  ][j0];
        float4 s1 = *(const float4*)&sp[w*2+1][j0];
        float4 d0 = *(const float4*)(D0 + j0);
        float4 d1 = *(const float4*)(D1 + j0);
        float4 p0, p1;
        p0.x = __expf(s0.x-m0); p0.y = __expf(s0.y-m0); p0.z = __expf(s0.z-m0); p0.w = __expf(s0.w-m0);
        p1.x = __expf(s1.x-m1); p1.y = __expf(s1.y-m1); p1.z = __expf(s1.z-m1); p1.w = __expf(s1.w-m1);
        sum0 += (p0.x+p0.y)+(p0.z+p0.w);
        sum1 += (p1.x+p1.y)+(p1.z+p1.w);
        sd0 = fmaf(p0.x,d0.x,sd0); sd0 = fmaf(p0.y,d0.y,sd0); sd0 = fmaf(p0.z,d0.z,sd0); sd0 = fmaf(p0.w,d0.w,sd0);
        sd1 = fmaf(p1.x,d1.x,sd1); sd1 = fmaf(p1.y,d1.y,sd1); sd1 = fmaf(p1.z,d1.z,sd1); sd1 = fmaf(p1.w,d1.w,sd1);
        *(float4*)&sp[w*2  ][j0] = p0;
        *(float4*)&sp[w*2+1][j0] = p1;
    }
    sum0 = warpSum(sum0); sum1 = warpSum(sum1);
    sd0  = warpSum(sd0);  sd1  = warpSum(sd1);
    float inv0 = 1.f/sum0, inv1 = 1.f/sum1;
    __syncwarp();

    const float* Vp = v + bh*SN*HD;
    const float4* p0v = (const float4*)sp[w*2];
    const float4* p1v = (const float4*)sp[w*2+1];
    float a00=0.f,a01=0.f,a02=0.f,a03=0.f;
    float a10=0.f,a11=0.f,a12=0.f,a13=0.f;
    #pragma unroll 4
    for(int j4=0;j4<128;j4++){
        float4 p0 = p0v[j4];
        float4 p1 = p1v[j4];
        const float* vb = Vp + j4*128 + lane;
        float v0 = vb[0], v1 = vb[32], v2 = vb[64], v3 = vb[96];
        a00 = fmaf(p0.x,v0,a00); a01 = fmaf(p0.y,v1,a01);
        a02 = fmaf(p0.z,v2,a02); a03 = fmaf(p0.w,v3,a03);
        a10 = fmaf(p1.x,v0,a10); a11 = fmaf(p1.y,v1,a11);
        a12 = fmaf(p1.z,v2,a12); a13 = fmaf(p1.w,v3,a13);
    }
    float a0 = (a00+a01)+(a02+a03);
    float a1 = (a10+a11)+(a12+a13);
    float wl = We[h*32 + lane], bl = be[h*32 + lane];
    out[((b*SN + i0)*NH + h)*HD + lane] = a0*inv0 + (sd0*inv0)*wl + bl;
    out[((b*SN + i1)*NH + h)*HD + lane] = a1*inv1 + (sd1*inv1)*wl + bl;
}

// ---------------- fused gate + residual + next-layer LN stats ----------------
__global__ void __launch_bounds__(256) k_gate(const float* __restrict__ o, const float* __restrict__ wg,
                                              float* __restrict__ nodes,
                                              float* __restrict__ mu, float* __restrict__ rs){
    int w = threadIdx.x >> 5, lane = threadIdx.x & 31;
    int tok = blockIdx.x*8 + w;
    const float* op = o + tok*DIM;
    float* np = nodes + tok*DIM;
    float ov[8], nv[8];
    float s = 0.f;
    #pragma unroll
    for(int k=0;k<8;k++){
        int c = lane + k*32;
        ov[k] = op[c]; nv[k] = np[c];
        s = fmaf(ov[k], wg[c] + wg[512+c], s);
        s = fmaf(nv[k], wg[256+c] - wg[512+c], s);
    }
    s = warpSum(s);
    float g = 1.f / (1.f + __expf(-s));
    float vs = 0.f;
    float newv[8];
    #pragma unroll
    for(int k=0;k<8;k++){
        newv[k] = ov[k]*g + nv[k]*(1.f - g);
        vs += newv[k];
    }
    vs = warpSum(vs);
    float mean = vs * (1.f/DIM);
    float v2 = 0.f;
    #pragma unroll
    for(int k=0;k<8;k++){
        int c = lane + k*32;
        np[c] = newv[k];
        float d = newv[k] - mean;
        v2 = fmaf(d, d, v2);
    }
    v2 = warpSum(v2);
    if(lane == 0){ mu[tok] = mean; rs[tok] = rsqrtf(v2*(1.f/DIM) + 1e-5f); }
}

// ---------------- decoder ----------------
__global__ void __launch_bounds__(256) k_decode(const float* __restrict__ nodes, const float* __restrict__ Wd,
                                                float* __restrict__ out){
    int w = threadIdx.x >> 5, lane = threadIdx.x & 31;
    int tok = blockIdx.x*8 + w;
    const float* np = nodes + tok*DIM;
    float a0 = 0.f, a1 = 0.f, a2 = 0.f;
    #pragma unroll
    for(int k0=0;k0<8;k0++){
        int k = lane + k0*32;
        float nv = np[k];
        a0 = fmaf(nv, Wd[k*3+0], a0);
        a1 = fmaf(nv, Wd[k*3+1], a1);
        a2 = fmaf(nv, Wd[k*3+2], a2);
    }
    a0 = warpSum(a0); a1 = warpSum(a1); a2 = warpSum(a2);
    if(lane == 0){
        out[tok*3+0] = a0; out[tok*3+1] = a1; out[tok*3+2] = a2;
    }
}

// ---------------- launch ----------------
extern "C" void kernel_launch(void* const* d_in, const int* in_sizes, int n_in,
                              void* d_out, int out_size){
    (void)in_sizes; (void)n_in; (void)out_size;
    const float* x     = (const float*)d_in[0];
    const float* t     = (const float*)d_in[1];
    const float* W_enc = (const float*)d_in[2];
    const float* W_dec = (const float*)d_in[3];
    const float* ln_g  = (const float*)d_in[4];
    const float* ln_b  = (const float*)d_in[5];
    const float* Wq    = (const float*)d_in[6];
    const float* bq    = (const float*)d_in[7];
    const float* Wkv   = (const float*)d_in[8];
    const float* bkv   = (const float*)d_in[9];
    const float* We    = (const float*)d_in[10];
    const float* be    = (const float*)d_in[11];
    const float* Wo    = (const float*)d_in[12];
    const float* bo    = (const float*)d_in[13];
    const float* Wg    = (const float*)d_in[14];
    float* out = (float*)d_out;

    float *dist,*nodes,*mu,*rs,*qkv,*q,*kt,*v,*qwe,*qbe,*attno,*ofull,*tab;
    cudaGetSymbolAddress((void**)&dist,  g_dist);
    cudaGetSymbolAddress((void**)&nodes, g_nodes);
    cudaGetSymbolAddress((void**)&mu,    g_mu);
    cudaGetSymbolAddress((void**)&rs,    g_rs);
    cudaGetSymbolAddress((void**)&qkv,   g_qkv);
    cudaGetSymbolAddress((void**)&q,     g_q);
    cudaGetSymbolAddress((void**)&kt,    g_kt);
    cudaGetSymbolAddress((void**)&v,     g_v);
    cudaGetSymbolAddress((void**)&qwe,   g_qwe);
    cudaGetSymbolAddress((void**)&qbe,   g_qbe);
    cudaGetSymbolAddress((void**)&attno, g_attno);
    cudaGetSymbolAddress((void**)&ofull, g_out);
    cudaGetSymbolAddress((void**)&tab,   g_tab);

    k_tab   <<<32,256>>>(tab);
    k_dist  <<<2048,256>>>(x, dist);
    k_encode<<<1024,256>>>(x, t, W_enc, nodes, mu, rs);

    for(int l=0;l<2;l++){
        k_qkv<<<dim3(12,16),256>>>(nodes, mu, rs, ln_g + l*DIM, ln_b + l*DIM,
                                   Wq + l*DIM*DIM, bq + l*DIM,
                                   Wkv + l*DIM*2*DIM, bkv + l*2*DIM, qkv);
        k_rot<<<1024,256>>>(qkv, We + l*DIM, be + l*DIM, tab, q, qwe, qbe, kt, v);
        k_attn2<<<512,256>>>(q, kt, v, qwe, qbe, dist, We + l*DIM, be + l*DIM, attno);
        k_gemmO<<<dim3(4,32),256>>>(attno, Wo + l*DIM*DIM, bo + l*DIM, ofull);
        k_gate<<<128,256>>>(ofull, Wg + l*3*DIM, nodes, mu, rs);
    }
    k_decode<<<128,256>>>(nodes, W_dec, out);
}

// round 6
// speedup vs baseline: 1.1602x; 1.1109x over previous
#include <cuda_runtime.h>
#include <math.h>

#define NB 2
#define SN 512
#define DIM 256
#define NH 8
#define HD 32
#define QSCALE 0.17677669529663689f   // 1/sqrt(32)
#define FREQC  0.5756462732485115f    // ln(10000)/16

// ---------------- scratch (device globals) ----------------
__device__ float g_dist [NB*SN*SN];
__device__ float g_nodes[NB*SN*DIM];
__device__ float g_mu   [NB*SN];
__device__ float g_rs   [NB*SN];
__device__ float g_qkv  [NB*SN*3*DIM];   // [tok][768] : q | k | v
__device__ float g_q    [NB*NH*SN*HD];   // [bh][i][d] rotary, *SCALE
__device__ float g_kt   [NB*NH*HD*SN];   // [bh][d][i] rotary
__device__ float g_v    [NB*NH*SN*HD];   // [bh][i][d]
__device__ float g_qwe  [NB*NH*SN];
__device__ float g_qbe  [NB*NH*SN];
__device__ float g_attno[NB*SN*DIM];
__device__ float g_out  [NB*SN*DIM];
__device__ float g_tab  [SN*32];         // [i][ cs(16) | sn(16) ]

// ---------------- helpers ----------------
__device__ __forceinline__ float warpSum(float v){
    #pragma unroll
    for(int o=16;o;o>>=1) v += __shfl_xor_sync(0xffffffffu, v, o);
    return v;
}
__device__ __forceinline__ float warpMax(float v){
    #pragma unroll
    for(int o=16;o;o>>=1) v = fmaxf(v, __shfl_xor_sync(0xffffffffu, v, o));
    return v;
}
__device__ __forceinline__ unsigned f2tf(float f){
    unsigned r; asm("cvt.rna.tf32.f32 %0, %1;" : "=r"(r) : "f"(f)); return r;
}
__device__ __forceinline__ void mma8(float* c, unsigned a0, unsigned a1, unsigned a2, unsigned a3,
                                     unsigned b0, unsigned b1){
    asm("mma.sync.aligned.m16n8k8.row.col.f32.tf32.tf32.f32 "
        "{%0,%1,%2,%3},{%4,%5,%6,%7},{%8,%9},{%0,%1,%2,%3};"
        : "+f"(c[0]),"+f"(c[1]),"+f"(c[2]),"+f"(c[3])
        : "r"(a0),"r"(a1),"r"(a2),"r"(a3),"r"(b0),"r"(b1));
}

// ---------------- rotary trig table ----------------
__global__ void __launch_bounds__(256) k_tab(float* __restrict__ tab){
    int idx = blockIdx.x*256 + threadIdx.x;   // < 8192
    int i = idx >> 4, fd = idx & 15;
    float fr = (float)i * expf(-(float)fd * FREQC);
    tab[i*32 + fd]      = cosf(fr);
    tab[i*32 + 16 + fd] = sinf(fr);
}

// ---------------- pairwise distances ----------------
__global__ void __launch_bounds__(256) k_dist(const float* __restrict__ x, float* __restrict__ dist){
    int idx = blockIdx.x*256 + threadIdx.x;
    int j = idx & 511; int rest = idx >> 9;
    int i = rest & 511; int b = rest >> 9;
    const float* xi = x + (b*SN + i)*3;
    const float* xj = x + (b*SN + j)*3;
    float d0 = xi[0]-xj[0], d1 = xi[1]-xj[1], d2 = xi[2]-xj[2];
    float q = d0*d0 + d1*d1 + d2*d2;
    dist[idx] = (q > 0.f) ? sqrtf(q) : 0.f;
}

// ---------------- encoder + LN stats (block per token) ----------------
__global__ void __launch_bounds__(256) k_encode(const float* __restrict__ x, const float* __restrict__ t,
                                                const float* __restrict__ W, float* __restrict__ nodes,
                                                float* __restrict__ mu, float* __restrict__ rs){
    int tok = blockIdx.x; int tid = threadIdx.x;
    const float* xp = x + tok*3;
    float v = xp[0]*W[tid] + xp[1]*W[256+tid] + xp[2]*W[512+tid] + t[tok]*W[768+tid];
    nodes[tok*DIM + tid] = v;

    __shared__ float sred[8]; __shared__ float sb;
    int w = tid>>5, lane = tid&31;
    float s = warpSum(v);
    if(lane==0) sred[w] = s;
    __syncthreads();
    if(tid < 32){ float t2 = (tid<8)? sred[tid] : 0.f; t2 = warpSum(t2); if(tid==0) sb = t2; }
    __syncthreads();
    float mean = sb * (1.f/DIM);
    float d = v - mean;
    float s2 = warpSum(d*d);
    __syncthreads();
    if(lane==0) sred[w] = s2;
    __syncthreads();
    if(tid < 32){ float t2 = (tid<8)? sred[tid] : 0.f; t2 = warpSum(t2); if(tid==0) sb = t2; }
    __syncthreads();
    if(tid==0){ mu[tok] = mean; rs[tok] = rsqrtf(sb*(1.f/DIM) + 1e-5f); }
}

// ============ tf32 tensor-core GEMM: BM=128, BN=64, BK=16, 256 thr, 8 warps ============
// QKV=true:  C[1024,768] = LN(A) @ [Wq|Wkv] + bias  (grid 12 x 8)
// QKV=false: C[1024,256] = A @ W1 + b1              (grid 4 x 8)
template<bool QKV>
__global__ void __launch_bounds__(256) k_gemm_tc(const float* __restrict__ A,
        const float* __restrict__ mu, const float* __restrict__ rs,
        const float* __restrict__ lng, const float* __restrict__ lnb,
        const float* __restrict__ W1, const float* __restrict__ b1,
        const float* __restrict__ W2, const float* __restrict__ b2,
        float* __restrict__ C){
    constexpr int BM=128, BK=16, BN=64, K=256;
    constexpr int LDC = QKV ? 768 : 256;
    __shared__ unsigned As[2][BM][BK+4];
    __shared__ unsigned Bs[2][BK][BN+8];
    int tx = threadIdx.x;
    int wid = tx>>5, lane = tx&31;
    int bcol = blockIdx.x*BN, brow = blockIdx.y*BM;

    const float* W; const float* bias; int ldb;
    if(QKV){
        if(bcol < 256){ W = W1 + bcol;        bias = b1 + bcol;        ldb = 256; }
        else          { W = W2 + (bcol-256);  bias = b2 + (bcol-256);  ldb = 512; }
    } else {            W = W1 + bcol;        bias = b1 + bcol;        ldb = 256; }

    int ar[2], akk[2];
    #pragma unroll
    for(int u=0;u<2;u++){ int f = tx + u*256; ar[u]=f>>2; akk[u]=(f&3)*4; }
    int bkr = tx>>4, bkc = (tx&15)*4;

    const float* Ab = A + brow*K;
    float muv[2]={0.f,0.f}, rsv[2]={1.f,1.f};
    if(QKV){
        #pragma unroll
        for(int u=0;u<2;u++){ muv[u] = mu[brow+ar[u]]; rsv[u] = rs[brow+ar[u]]; }
    }

    float4 ra[2], rb;
    // load tile 0
    #pragma unroll
    for(int u=0;u<2;u++){
        float4 v = *(const float4*)(Ab + ar[u]*K + akk[u]);
        if(QKV){
            float4 g = *(const float4*)(lng + akk[u]);
            float4 b = *(const float4*)(lnb + akk[u]);
            v.x = fmaf((v.x-muv[u])*rsv[u], g.x, b.x);
            v.y = fmaf((v.y-muv[u])*rsv[u], g.y, b.y);
            v.z = fmaf((v.z-muv[u])*rsv[u], g.z, b.z);
            v.w = fmaf((v.w-muv[u])*rsv[u], g.w, b.w);
        }
        ra[u] = v;
    }
    rb = *(const float4*)(W + bkr*ldb + bkc);
    #pragma unroll
    for(int u=0;u<2;u++)
        *(uint4*)&As[0][ar[u]][akk[u]] = make_uint4(f2tf(ra[u].x),f2tf(ra[u].y),f2tf(ra[u].z),f2tf(ra[u].w));
    *(uint4*)&Bs[0][bkr][bkc] = make_uint4(f2tf(rb.x),f2tf(rb.y),f2tf(rb.z),f2tf(rb.w));
    __syncthreads();

    int wm = (wid & 3)*32, wn = (wid >> 2)*32;
    float acc[2][4][4];
    #pragma unroll
    for(int mt=0;mt<2;mt++)
        #pragma unroll
        for(int nt=0;nt<4;nt++)
            #pragma unroll
            for(int e=0;e<4;e++) acc[mt][nt][e] = 0.f;

    const int NT = K/BK;   // 16
    for(int t=0;t<NT;t++){
        int buf = t&1;
        if(t+1<NT){
            int k0 = (t+1)*BK;
            #pragma unroll
            for(int u=0;u<2;u++){
                float4 v = *(const float4*)(Ab + ar[u]*K + k0 + akk[u]);
                if(QKV){
                    float4 g = *(const float4*)(lng + k0 + akk[u]);
                    float4 b = *(const float4*)(lnb + k0 + akk[u]);
                    v.x = fmaf((v.x-muv[u])*rsv[u], g.x, b.x);
                    v.y = fmaf((v.y-muv[u])*rsv[u], g.y, b.y);
                    v.z = fmaf((v.z-muv[u])*rsv[u], g.z, b.z);
                    v.w = fmaf((v.w-muv[u])*rsv[u], g.w, b.w);
                }
                ra[u] = v;
            }
            rb = *(const float4*)(W + (k0+bkr)*ldb + bkc);
        }
        #pragma unroll
        for(int ks=0;ks<2;ks++){
            int kq = ks*8 + (lane&3);
            unsigned a[2][4], b[4][2];
            int arow = wm + (lane>>2);
            #pragma unroll
            for(int mt=0;mt<2;mt++){
                int r = arow + mt*16;
                a[mt][0] = As[buf][r  ][kq];
                a[mt][1] = As[buf][r+8][kq];
                a[mt][2] = As[buf][r  ][kq+4];
                a[mt][3] = As[buf][r+8][kq+4];
            }
            int bc0 = wn + (lane>>2);
            #pragma unroll
            for(int nt=0;nt<4;nt++){
                b[nt][0] = Bs[buf][kq  ][bc0 + nt*8];
                b[nt][1] = Bs[buf][kq+4][bc0 + nt*8];
            }
            #pragma unroll
            for(int mt=0;mt<2;mt++)
                #pragma unroll
                for(int nt=0;nt<4;nt++)
                    mma8(acc[mt][nt], a[mt][0],a[mt][1],a[mt][2],a[mt][3], b[nt][0],b[nt][1]);
        }
        if(t+1<NT){
            int nb = buf^1;
            #pragma unroll
            for(int u=0;u<2;u++)
                *(uint4*)&As[nb][ar[u]][akk[u]] = make_uint4(f2tf(ra[u].x),f2tf(ra[u].y),f2tf(ra[u].z),f2tf(ra[u].w));
            *(uint4*)&Bs[nb][bkr][bkc] = make_uint4(f2tf(rb.x),f2tf(rb.y),f2tf(rb.z),f2tf(rb.w));
            __syncthreads();
        }
    }

    #pragma unroll
    for(int mt=0;mt<2;mt++){
        int r = brow + wm + mt*16 + (lane>>2);
        #pragma unroll
        for(int nt=0;nt<4;nt++){
            int lc = wn + nt*8 + (lane&3)*2;
            float bz0 = bias[lc], bz1 = bias[lc+1];
            float* c0p = C + r*LDC + bcol + lc;
            c0p[0] = acc[mt][nt][0] + bz0;
            c0p[1] = acc[mt][nt][1] + bz1;
            float* c1p = C + (r+8)*LDC + bcol + lc;
            c1p[0] = acc[mt][nt][2] + bz0;
            c1p[1] = acc[mt][nt][3] + bz1;
        }
    }
}

// ---------------- rotary Q/K (+ q.We, q.be) + V relayout (table trig) ----------------
__global__ void __launch_bounds__(256) k_rot(const float* __restrict__ qkv,
                                             const float* __restrict__ We, const float* __restrict__ be,
                                             const float* __restrict__ tab,
                                             float* __restrict__ q, float* __restrict__ qwe, float* __restrict__ qbe,
                                             float* __restrict__ kt, float* __restrict__ v){
    int bi = blockIdx.x;
    int b = bi >> 9, i = bi & 511;
    int h = threadIdx.x >> 5, d = threadIdx.x & 31;
    int bh = b*NH + h;
    const float* row = qkv + bi*768;
    int fd = d & 15;
    float cs = tab[i*32 + fd];
    float sn = tab[i*32 + 16 + fd];

    float qv = row[h*32 + d];
    float qo = row[h*32 + ((d+16)&31)];
    float qrot = (d < 16) ? -qo : qo;
    float qval = (qv*cs + qrot*sn) * QSCALE;
    q[(bh*SN + i)*HD + d] = qval;

    float kv = row[256 + h*32 + d];
    float ko = row[256 + h*32 + ((d+16)&31)];
    float krot = (d < 16) ? -ko : ko;
    kt[(bh*HD + d)*SN + i] = kv*cs + krot*sn;

    v[(bh*SN + i)*HD + d] = row[512 + h*32 + d];

    float dwe = warpSum(qval * We[h*32 + d]);
    float dbe = warpSum(qval * be[h*32 + d]);
    if(d == 0){ qwe[bh*SN + i] = dwe; qbe[bh*SN + i] = dbe; }
}

// ---------------- attention: warp handles 2 query rows ----------------
__global__ void __launch_bounds__(256) k_attn2(
    const float* __restrict__ q, const float* __restrict__ kt, const float* __restrict__ v,
    const float* __restrict__ qwe, const float* __restrict__ qbe, const float* __restrict__ dist,
    const float* __restrict__ We, const float* __restrict__ be, float* __restrict__ out)
{
    __shared__ __align__(16) float sp[16][512];
    int w = threadIdx.x >> 5, lane = threadIdx.x & 31;
    int bh = blockIdx.x >> 5;
    int chunk = blockIdx.x & 31;
    int b = bh >> 3, h = bh & 7;
    int i0 = chunk*16 + w*2, i1 = i0 + 1;

    float qr0[32], qr1[32];
    {
        float qv0 = q[(bh*SN + i0)*HD + lane];
        float qv1 = q[(bh*SN + i1)*HD + lane];
        #pragma unroll
        for(int d=0;d<32;d++){ qr0[d] = __shfl_sync(0xffffffffu, qv0, d);
                               qr1[d] = __shfl_sync(0xffffffffu, qv1, d); }
    }
    float cwe0 = qwe[bh*SN + i0], cwe1 = qwe[bh*SN + i1];
    float cbe0 = qbe[bh*SN + i0], cbe1 = qbe[bh*SN + i1];
    const float* Kt = kt + bh*HD*SN;
    const float* D0 = dist + (b*SN + i0)*SN;
    const float* D1 = dist + (b*SN + i1)*SN;

    float m0 = -1e30f, m1 = -1e30f;
    #pragma unroll
    for(int cb=0;cb<4;cb++){
        int j0 = cb*128 + lane*4;
        float4 s0 = make_float4(cbe0,cbe0,cbe0,cbe0);
        float4 s1 = make_float4(cbe1,cbe1,cbe1,cbe1);
        #pragma unroll
        for(int d=0;d<32;d++){
            float4 kk = *(const float4*)(Kt + d*SN + j0);
            s0.x = fmaf(qr0[d], kk.x, s0.x); s0.y = fmaf(qr0[d], kk.y, s0.y);
            s0.z = fmaf(qr0[d], kk.z, s0.z); s0.w = fmaf(qr0[d], kk.w, s0.w);
            s1.x = fmaf(qr1[d], kk.x, s1.x); s1.y = fmaf(qr1[d], kk.y, s1.y);
            s1.z = fmaf(qr1[d], kk.z, s1.z); s1.w = fmaf(qr1[d], kk.w, s1.w);
        }
        float4 d0 = *(const float4*)(D0 + j0);
        float4 d1 = *(const float4*)(D1 + j0);
        s0.x = fmaf(d0.x, cwe0, s0.x); s0.y = fmaf(d0.y, cwe0, s0.y);
        s0.z = fmaf(d0.z, cwe0, s0.z); s0.w = fmaf(d0.w, cwe0, s0.w);
        s1.x = fmaf(d1.x, cwe1, s1.x); s1.y = fmaf(d1.y, cwe1, s1.y);
        s1.z = fmaf(d1.z, cwe1, s1.z); s1.w = fmaf(d1.w, cwe1, s1.w);
        *(float4*)&sp[w*2  ][j0] = s0;
        *(float4*)&sp[w*2+1][j0] = s1;
        m0 = fmaxf(m0, fmaxf(fmaxf(s0.x,s0.y), fmaxf(s0.z,s0.w)));
        m1 = fmaxf(m1, fmaxf(fmaxf(s1.x,s1.y), fmaxf(s1.z,s1.w)));
    }
    m0 = warpMax(m0); m1 = warpMax(m1);

    float sum0 = 0.f, sum1 = 0.f, sd0 = 0.f, sd1 = 0.f;
    #pragma unroll
    for(int cb=0;cb<4;cb++){
        int j0 = cb*128 + lane*4;
        float4 s0 = *(const float4*)&sp[w*2  ][j0];
        float4 s1 = *(const float4*)&sp[w*2+1][j0];
        float4 d0 = *(const float4*)(D0 + j0);
        float4 d1 = *(const float4*)(D1 + j0);
        float4 p0, p1;
        p0.x = __expf(s0.x-m0); p0.y = __expf(s0.y-m0); p0.z = __expf(s0.z-m0); p0.w = __expf(s0.w-m0);
        p1.x = __expf(s1.x-m1); p1.y = __expf(s1.y-m1); p1.z = __expf(s1.z-m1); p1.w = __expf(s1.w-m1);
        sum0 += (p0.x+p0.y)+(p0.z+p0.w);
        sum1 += (p1.x+p1.y)+(p1.z+p1.w);
        sd0 = fmaf(p0.x,d0.x,sd0); sd0 = fmaf(p0.y,d0.y,sd0); sd0 = fmaf(p0.z,d0.z,sd0); sd0 = fmaf(p0.w,d0.w,sd0);
        sd1 = fmaf(p1.x,d1.x,sd1); sd1 = fmaf(p1.y,d1.y,sd1); sd1 = fmaf(p1.z,d1.z,sd1); sd1 = fmaf(p1.w,d1.w,sd1);
        *(float4*)&sp[w*2  ][j0] = p0;
        *(float4*)&sp[w*2+1][j0] = p1;
    }
    sum0 = warpSum(sum0); sum1 = warpSum(sum1);
    sd0  = warpSum(sd0);  sd1  = warpSum(sd1);
    float inv0 = 1.f/sum0, inv1 = 1.f/sum1;
    __syncwarp();

    const float* Vp = v + bh*SN*HD;
    const float4* p0v = (const float4*)sp[w*2];
    const float4* p1v = (const float4*)sp[w*2+1];
    float a00=0.f,a01=0.f,a02=0.f,a03=0.f;
    float a10=0.f,a11=0.f,a12=0.f,a13=0.f;
    #pragma unroll 4
    for(int j4=0;j4<128;j4++){
        float4 p0 = p0v[j4];
        float4 p1 = p1v[j4];
        const float* vb = Vp + j4*128 + lane;
        float v0 = vb[0], v1 = vb[32], v2 = vb[64], v3 = vb[96];
        a00 = fmaf(p0.x,v0,a00); a01 = fmaf(p0.y,v1,a01);
        a02 = fmaf(p0.z,v2,a02); a03 = fmaf(p0.w,v3,a03);
        a10 = fmaf(p1.x,v0,a10); a11 = fmaf(p1.y,v1,a11);
        a12 = fmaf(p1.z,v2,a12); a13 = fmaf(p1.w,v3,a13);
    }
    float a0 = (a00+a01)+(a02+a03);
    float a1 = (a10+a11)+(a12+a13);
    float wl = We[h*32 + lane], bl = be[h*32 + lane];
    out[((b*SN + i0)*NH + h)*HD + lane] = a0*inv0 + (sd0*inv0)*wl + bl;
    out[((b*SN + i1)*NH + h)*HD + lane] = a1*inv1 + (sd1*inv1)*wl + bl;
}

// ---------------- fused gate + residual + next-layer LN stats ----------------
__global__ void __launch_bounds__(256) k_gate(const float* __restrict__ o, const float* __restrict__ wg,
                                              float* __restrict__ nodes,
                                              float* __restrict__ mu, float* __restrict__ rs){
    int w = threadIdx.x >> 5, lane = threadIdx.x & 31;
    int tok = blockIdx.x*8 + w;
    const float* op = o + tok*DIM;
    float* np = nodes + tok*DIM;
    float ov[8], nv[8];
    float s = 0.f;
    #pragma unroll
    for(int k=0;k<8;k++){
        int c = lane + k*32;
        ov[k] = op[c]; nv[k] = np[c];
        s = fmaf(ov[k], wg[c] + wg[512+c], s);
        s = fmaf(nv[k], wg[256+c] - wg[512+c], s);
    }
    s = warpSum(s);
    float g = 1.f / (1.f + __expf(-s));
    float vs = 0.f;
    float newv[8];
    #pragma unroll
    for(int k=0;k<8;k++){
        newv[k] = ov[k]*g + nv[k]*(1.f - g);
        vs += newv[k];
    }
    vs = warpSum(vs);
    float mean = vs * (1.f/DIM);
    float v2 = 0.f;
    #pragma unroll
    for(int k=0;k<8;k++){
        int c = lane + k*32;
        np[c] = newv[k];
        float d = newv[k] - mean;
        v2 = fmaf(d, d, v2);
    }
    v2 = warpSum(v2);
    if(lane == 0){ mu[tok] = mean; rs[tok] = rsqrtf(v2*(1.f/DIM) + 1e-5f); }
}

// ---------------- decoder ----------------
__global__ void __launch_bounds__(256) k_decode(const float* __restrict__ nodes, const float* __restrict__ Wd,
                                                float* __restrict__ out){
    int w = threadIdx.x >> 5, lane = threadIdx.x & 31;
    int tok = blockIdx.x*8 + w;
    const float* np = nodes + tok*DIM;
    float a0 = 0.f, a1 = 0.f, a2 = 0.f;
    #pragma unroll
    for(int k0=0;k0<8;k0++){
        int k = lane + k0*32;
        float nv = np[k];
        a0 = fmaf(nv, Wd[k*3+0], a0);
        a1 = fmaf(nv, Wd[k*3+1], a1);
        a2 = fmaf(nv, Wd[k*3+2], a2);
    }
    a0 = warpSum(a0); a1 = warpSum(a1); a2 = warpSum(a2);
    if(lane == 0){
        out[tok*3+0] = a0; out[tok*3+1] = a1; out[tok*3+2] = a2;
    }
}

// ---------------- launch ----------------
extern "C" void kernel_launch(void* const* d_in, const int* in_sizes, int n_in,
                              void* d_out, int out_size){
    (void)in_sizes; (void)n_in; (void)out_size;
    const float* x     = (const float*)d_in[0];
    const float* t     = (const float*)d_in[1];
    const float* W_enc = (const float*)d_in[2];
    const float* W_dec = (const float*)d_in[3];
    const float* ln_g  = (const float*)d_in[4];
    const float* ln_b  = (const float*)d_in[5];
    const float* Wq    = (const float*)d_in[6];
    const float* bq    = (const float*)d_in[7];
    const float* Wkv   = (const float*)d_in[8];
    const float* bkv   = (const float*)d_in[9];
    const float* We    = (const float*)d_in[10];
    const float* be    = (const float*)d_in[11];
    const float* Wo    = (const float*)d_in[12];
    const float* bo    = (const float*)d_in[13];
    const float* Wg    = (const float*)d_in[14];
    float* out = (float*)d_out;

    float *dist,*nodes,*mu,*rs,*qkv,*q,*kt,*v,*qwe,*qbe,*attno,*ofull,*tab;
    cudaGetSymbolAddress((void**)&dist,  g_dist);
    cudaGetSymbolAddress((void**)&nodes, g_nodes);
    cudaGetSymbolAddress((void**)&mu,    g_mu);
    cudaGetSymbolAddress((void**)&rs,    g_rs);
    cudaGetSymbolAddress((void**)&qkv,   g_qkv);
    cudaGetSymbolAddress((void**)&q,     g_q);
    cudaGetSymbolAddress((void**)&kt,    g_kt);
    cudaGetSymbolAddress((void**)&v,     g_v);
    cudaGetSymbolAddress((void**)&qwe,   g_qwe);
    cudaGetSymbolAddress((void**)&qbe,   g_qbe);
    cudaGetSymbolAddress((void**)&attno, g_attno);
    cudaGetSymbolAddress((void**)&ofull, g_out);
    cudaGetSymbolAddress((void**)&tab,   g_tab);

    k_tab   <<<32,256>>>(tab);
    k_dist  <<<2048,256>>>(x, dist);
    k_encode<<<1024,256>>>(x, t, W_enc, nodes, mu, rs);

    for(int l=0;l<2;l++){
        k_gemm_tc<true><<<dim3(12,8),256>>>(nodes, mu, rs, ln_g + l*DIM, ln_b + l*DIM,
                                            Wq + l*DIM*DIM, bq + l*DIM,
                                            Wkv + l*DIM*2*DIM, bkv + l*2*DIM, qkv);
        k_rot<<<1024,256>>>(qkv, We + l*DIM, be + l*DIM, tab, q, qwe, qbe, kt, v);
        k_attn2<<<512,256>>>(q, kt, v, qwe, qbe, dist, We + l*DIM, be + l*DIM, attno);
        k_gemm_tc<false><<<dim3(4,8),256>>>(attno, nullptr, nullptr, nullptr, nullptr,
                                            Wo + l*DIM*DIM, bo + l*DIM, nullptr, nullptr, ofull);
        k_gate<<<128,256>>>(ofull, Wg + l*3*DIM, nodes, mu, rs);
    }
    k_decode<<<128,256>>>(nodes, W_dec, out);
}

// round 7
// speedup vs baseline: 1.2370x; 1.0662x over previous
#include <cuda_runtime.h>
#include <math.h>

#define NB 2
#define SN 512
#define DIM 256
#define NH 8
#define HD 32
#define QSCALE 0.17677669529663689f   // 1/sqrt(32)
#define FREQC  0.5756462732485115f    // ln(10000)/16

// ---------------- scratch (device globals) ----------------
__device__ __align__(256) float g_dist [NB*SN*SN];
__device__ __align__(256) float g_nodes[NB*SN*DIM];
__device__ __align__(256) float g_mu   [NB*SN];
__device__ __align__(256) float g_rs   [NB*SN];
__device__ __align__(256) float g_h    [NB*SN*DIM];      // LN'd, tf32-rounded
__device__ __align__(256) float g_qkv  [NB*SN*3*DIM];
__device__ __align__(256) float g_q    [NB*NH*SN*HD];
__device__ __align__(256) float g_kt   [NB*NH*HD*SN];
__device__ __align__(256) float g_v    [NB*NH*SN*HD];
__device__ __align__(256) float g_qwe  [NB*NH*SN];
__device__ __align__(256) float g_qbe  [NB*NH*SN];
__device__ __align__(256) float g_attno[NB*SN*DIM];      // tf32-rounded
__device__ __align__(256) float g_out  [NB*SN*DIM];
__device__ __align__(256) float g_tab  [SN*32];
__device__ __align__(256) float g_wq   [2*DIM*DIM];      // tf32-rounded weights
__device__ __align__(256) float g_wkv  [2*DIM*2*DIM];
__device__ __align__(256) float g_wo   [2*DIM*DIM];

// ---------------- helpers ----------------
__device__ __forceinline__ float warpSum(float v){
    #pragma unroll
    for(int o=16;o;o>>=1) v += __shfl_xor_sync(0xffffffffu, v, o);
    return v;
}
__device__ __forceinline__ float warpMax(float v){
    #pragma unroll
    for(int o=16;o;o>>=1) v = fmaxf(v, __shfl_xor_sync(0xffffffffu, v, o));
    return v;
}
__device__ __forceinline__ unsigned f2tf(float f){
    unsigned r; asm("cvt.rna.tf32.f32 %0, %1;" : "=r"(r) : "f"(f)); return r;
}
__device__ __forceinline__ float tfround(float f){ return __uint_as_float(f2tf(f)); }
__device__ __forceinline__ void mma8(float* c, unsigned a0, unsigned a1, unsigned a2, unsigned a3,
                                     unsigned b0, unsigned b1){
    asm("mma.sync.aligned.m16n8k8.row.col.f32.tf32.tf32.f32 "
        "{%0,%1,%2,%3},{%4,%5,%6,%7},{%8,%9},{%0,%1,%2,%3};"
        : "+f"(c[0]),"+f"(c[1]),"+f"(c[2]),"+f"(c[3])
        : "r"(a0),"r"(a1),"r"(a2),"r"(a3),"r"(b0),"r"(b1));
}
__device__ __forceinline__ void cpa16(unsigned s, const void* g){
    asm volatile("cp.async.cg.shared.global [%0], [%1], 16;" :: "r"(s), "l"(g));
}

// ---------------- weight pre-rounding (once) ----------------
__global__ void __launch_bounds__(256) k_cvtW(const float* __restrict__ Wq, const float* __restrict__ Wkv,
                                              const float* __restrict__ Wo,
                                              float* __restrict__ wq, float* __restrict__ wkv,
                                              float* __restrict__ wo){
    int i = blockIdx.x*256 + threadIdx.x;          // < 524288
    if(i < 131072)       wq[i]         = tfround(Wq[i]);
    else if(i < 393216)  wkv[i-131072] = tfround(Wkv[i-131072]);
    else                 wo[i-393216]  = tfround(Wo[i-393216]);
}

// ---------------- rotary trig table ----------------
__global__ void __launch_bounds__(256) k_tab(float* __restrict__ tab){
    int idx = blockIdx.x*256 + threadIdx.x;
    int i = idx >> 4, fd = idx & 15;
    float fr = (float)i * expf(-(float)fd * FREQC);
    tab[i*32 + fd]      = cosf(fr);
    tab[i*32 + 16 + fd] = sinf(fr);
}

// ---------------- pairwise distances ----------------
__global__ void __launch_bounds__(256) k_dist(const float* __restrict__ x, float* __restrict__ dist){
    int idx = blockIdx.x*256 + threadIdx.x;
    int j = idx & 511; int rest = idx >> 9;
    int i = rest & 511; int b = rest >> 9;
    const float* xi = x + (b*SN + i)*3;
    const float* xj = x + (b*SN + j)*3;
    float d0 = xi[0]-xj[0], d1 = xi[1]-xj[1], d2 = xi[2]-xj[2];
    float q = d0*d0 + d1*d1 + d2*d2;
    dist[idx] = (q > 0.f) ? sqrtf(q) : 0.f;
}

// ---------------- encoder + LN stats ----------------
__global__ void __launch_bounds__(256) k_encode(const float* __restrict__ x, const float* __restrict__ t,
                                                const float* __restrict__ W, float* __restrict__ nodes,
                                                float* __restrict__ mu, float* __restrict__ rs){
    int tok = blockIdx.x; int tid = threadIdx.x;
    const float* xp = x + tok*3;
    float v = xp[0]*W[tid] + xp[1]*W[256+tid] + xp[2]*W[512+tid] + t[tok]*W[768+tid];
    nodes[tok*DIM + tid] = v;

    __shared__ float sred[8]; __shared__ float sb;
    int w = tid>>5, lane = tid&31;
    float s = warpSum(v);
    if(lane==0) sred[w] = s;
    __syncthreads();
    if(tid < 32){ float t2 = (tid<8)? sred[tid] : 0.f; t2 = warpSum(t2); if(tid==0) sb = t2; }
    __syncthreads();
    float mean = sb * (1.f/DIM);
    float d = v - mean;
    float s2 = warpSum(d*d);
    __syncthreads();
    if(lane==0) sred[w] = s2;
    __syncthreads();
    if(tid < 32){ float t2 = (tid<8)? sred[tid] : 0.f; t2 = warpSum(t2); if(tid==0) sb = t2; }
    __syncthreads();
    if(tid==0){ mu[tok] = mean; rs[tok] = rsqrtf(sb*(1.f/DIM) + 1e-5f); }
}

// ---------------- LN apply + tf32 round ----------------
__global__ void __launch_bounds__(256) k_ln(const float* __restrict__ nodes,
                                            const float* __restrict__ mu, const float* __restrict__ rs,
                                            const float* __restrict__ g, const float* __restrict__ b,
                                            float* __restrict__ h){
    int idx = blockIdx.x*256 + threadIdx.x;
    int tok = idx >> 8, c = idx & 255;
    float v = fmaf((nodes[idx]-mu[tok])*rs[tok], g[c], b[c]);
    h[idx] = tfround(v);
}

// ============ tf32 tensor-core GEMM, cp.async 3-stage: BM=128, BN=64, BK=16 ============
// A, W pre-rounded to tf32-in-f32. QKV: grid (12,8), C[1024,768]. else grid (4,8), C[1024,256].
template<bool QKV>
__global__ void __launch_bounds__(256) k_gemm_tc(const float* __restrict__ A,
        const float* __restrict__ W1, const float* __restrict__ b1,
        const float* __restrict__ W2, const float* __restrict__ b2,
        float* __restrict__ C){
    constexpr int BM=128, BK=16, BN=64, K=256, NST=3;
    constexpr int LDC = QKV ? 768 : 256;
    constexpr int ASZ = BM*(BK+4), BSZ = BK*(BN+8);
    __shared__ __align__(16) float As[NST][BM][BK+4];
    __shared__ __align__(16) float Bs[NST][BK][BN+8];
    int tx = threadIdx.x;
    int wid = tx>>5, lane = tx&31;
    int bcol = blockIdx.x*BN, brow = blockIdx.y*BM;

    const float* W; const float* bias; int ldb;
    if(QKV){
        if(bcol < 256){ W = W1 + bcol;        bias = b1 + bcol;        ldb = 256; }
        else          { W = W2 + (bcol-256);  bias = b2 + (bcol-256);  ldb = 512; }
    } else {            W = W1 + bcol;        bias = b1 + bcol;        ldb = 256; }

    int ar[2], akk[2];
    #pragma unroll
    for(int u=0;u<2;u++){ int f = tx + u*256; ar[u]=f>>2; akk[u]=(f&3)*4; }
    int bkr = tx>>4, bkc = (tx&15)*4;

    const float* Ab = A + brow*K;
    unsigned sA = (unsigned)__cvta_generic_to_shared(&As[0][0][0]);
    unsigned sB = (unsigned)__cvta_generic_to_shared(&Bs[0][0][0]);
    unsigned sa0 = sA + (ar[0]*(BK+4) + akk[0])*4u;
    unsigned sa1 = sA + (ar[1]*(BK+4) + akk[1])*4u;
    unsigned sb0 = sB + (bkr*(BN+8) + bkc)*4u;
    const float* ga0 = Ab + ar[0]*K + akk[0];
    const float* ga1 = Ab + ar[1]*K + akk[1];
    const float* gb0 = W + bkr*ldb + bkc;

    const int NT = K/BK;   // 16
    // prologue: stages 0..2
    #pragma unroll
    for(int s=0;s<NST;s++){
        cpa16(sa0 + s*ASZ*4u, ga0 + s*BK);
        cpa16(sa1 + s*ASZ*4u, ga1 + s*BK);
        cpa16(sb0 + s*BSZ*4u, gb0 + s*BK*ldb);
        asm volatile("cp.async.commit_group;" ::: "memory");
    }

    int wm = (wid & 3)*32, wn = (wid >> 2)*32;
    float acc[2][4][4];
    #pragma unroll
    for(int mt=0;mt<2;mt++)
        #pragma unroll
        for(int nt=0;nt<4;nt++)
            #pragma unroll
            for(int e=0;e<4;e++) acc[mt][nt][e] = 0.f;

    for(int t=0;t<NT;t++){
        asm volatile("cp.async.wait_group 2;" ::: "memory");
        __syncthreads();
        int buf = t % NST;
        #pragma unroll
        for(int ks=0;ks<2;ks++){
            int kq = ks*8 + (lane&3);
            unsigned a[2][4], b[4][2];
            int arow = wm + (lane>>2);
            #pragma unroll
            for(int mt=0;mt<2;mt++){
                int r = arow + mt*16;
                a[mt][0] = __float_as_uint(As[buf][r  ][kq]);
                a[mt][1] = __float_as_uint(As[buf][r+8][kq]);
                a[mt][2] = __float_as_uint(As[buf][r  ][kq+4]);
                a[mt][3] = __float_as_uint(As[buf][r+8][kq+4]);
            }
            int bc0 = wn + (lane>>2);
            #pragma unroll
            for(int nt=0;nt<4;nt++){
                b[nt][0] = __float_as_uint(Bs[buf][kq  ][bc0 + nt*8]);
                b[nt][1] = __float_as_uint(Bs[buf][kq+4][bc0 + nt*8]);
            }
            #pragma unroll
            for(int mt=0;mt<2;mt++)
                #pragma unroll
                for(int nt=0;nt<4;nt++)
                    mma8(acc[mt][nt], a[mt][0],a[mt][1],a[mt][2],a[mt][3], b[nt][0],b[nt][1]);
        }
        __syncthreads();
        int nt_ = t + NST;
        if(nt_ < NT){
            cpa16(sa0 + buf*ASZ*4u, ga0 + nt_*BK);
            cpa16(sa1 + buf*ASZ*4u, ga1 + nt_*BK);
            cpa16(sb0 + buf*BSZ*4u, gb0 + nt_*BK*ldb);
        }
        asm volatile("cp.async.commit_group;" ::: "memory");
    }

    #pragma unroll
    for(int mt=0;mt<2;mt++){
        int r = brow + wm + mt*16 + (lane>>2);
        #pragma unroll
        for(int nt=0;nt<4;nt++){
            int lc = wn + nt*8 + (lane&3)*2;
            float bz0 = bias[lc], bz1 = bias[lc+1];
            float* c0p = C + r*LDC + bcol + lc;
            c0p[0] = acc[mt][nt][0] + bz0;
            c0p[1] = acc[mt][nt][1] + bz1;
            float* c1p = C + (r+8)*LDC + bcol + lc;
            c1p[0] = acc[mt][nt][2] + bz0;
            c1p[1] = acc[mt][nt][3] + bz1;
        }
    }
}

// ---------------- rotary Q/K (+ q.We, q.be) + V relayout (table trig) ----------------
__global__ void __launch_bounds__(256) k_rot(const float* __restrict__ qkv,
                                             const float* __restrict__ We, const float* __restrict__ be,
                                             const float* __restrict__ tab,
                                             float* __restrict__ q, float* __restrict__ qwe, float* __restrict__ qbe,
                                             float* __restrict__ kt, float* __restrict__ v){
    int bi = blockIdx.x;
    int b = bi >> 9, i = bi & 511;
    int h = threadIdx.x >> 5, d = threadIdx.x & 31;
    int bh = b*NH + h;
    const float* row = qkv + bi*768;
    int fd = d & 15;
    float cs = tab[i*32 + fd];
    float sn = tab[i*32 + 16 + fd];

    float qv = row[h*32 + d];
    float qo = row[h*32 + ((d+16)&31)];
    float qrot = (d < 16) ? -qo : qo;
    float qval = (qv*cs + qrot*sn) * QSCALE;
    q[(bh*SN + i)*HD + d] = qval;

    float kv = row[256 + h*32 + d];
    float ko = row[256 + h*32 + ((d+16)&31)];
    float krot = (d < 16) ? -ko : ko;
    kt[(bh*HD + d)*SN + i] = kv*cs + krot*sn;

    v[(bh*SN + i)*HD + d] = row[512 + h*32 + d];

    float dwe = warpSum(qval * We[h*32 + d]);
    float dbe = warpSum(qval * be[h*32 + d]);
    if(d == 0){ qwe[bh*SN + i] = dwe; qbe[bh*SN + i] = dbe; }
}

// ---------------- attention: warp handles 2 query rows ----------------
__global__ void __launch_bounds__(256) k_attn2(
    const float* __restrict__ q, const float* __restrict__ kt, const float* __restrict__ v,
    const float* __restrict__ qwe, const float* __restrict__ qbe, const float* __restrict__ dist,
    const float* __restrict__ We, const float* __restrict__ be, float* __restrict__ out)
{
    __shared__ __align__(16) float sp[16][512];
    int w = threadIdx.x >> 5, lane = threadIdx.x & 31;
    int bh = blockIdx.x >> 5;
    int chunk = blockIdx.x & 31;
    int b = bh >> 3, h = bh & 7;
    int i0 = chunk*16 + w*2, i1 = i0 + 1;

    float qr0[32], qr1[32];
    {
        float qv0 = q[(bh*SN + i0)*HD + lane];
        float qv1 = q[(bh*SN + i1)*HD + lane];
        #pragma unroll
        for(int d=0;d<32;d++){ qr0[d] = __shfl_sync(0xffffffffu, qv0, d);
                               qr1[d] = __shfl_sync(0xffffffffu, qv1, d); }
    }
    float cwe0 = qwe[bh*SN + i0], cwe1 = qwe[bh*SN + i1];
    float cbe0 = qbe[bh*SN + i0], cbe1 = qbe[bh*SN + i1];
    const float* Kt = kt + bh*HD*SN;
    const float* D0 = dist + (b*SN + i0)*SN;
    const float* D1 = dist + (b*SN + i1)*SN;

    float m0 = -1e30f, m1 = -1e30f;
    #pragma unroll
    for(int cb=0;cb<4;cb++){
        int j0 = cb*128 + lane*4;
        float4 s0 = make_float4(cbe0,cbe0,cbe0,cbe0);
        float4 s1 = make_float4(cbe1,cbe1,cbe1,cbe1);
        #pragma unroll
        for(int d=0;d<32;d++){
            float4 kk = *(const float4*)(Kt + d*SN + j0);
            s0.x = fmaf(qr0[d], kk.x, s0.x); s0.y = fmaf(qr0[d], kk.y, s0.y);
            s0.z = fmaf(qr0[d], kk.z, s0.z); s0.w = fmaf(qr0[d], kk.w, s0.w);
            s1.x = fmaf(qr1[d], kk.x, s1.x); s1.y = fmaf(qr1[d], kk.y, s1.y);
            s1.z = fmaf(qr1[d], kk.z, s1.z); s1.w = fmaf(qr1[d], kk.w, s1.w);
        }
        float4 d0 = *(const float4*)(D0 + j0);
        float4 d1 = *(const float4*)(D1 + j0);
        s0.x = fmaf(d0.x, cwe0, s0.x); s0.y = fmaf(d0.y, cwe0, s0.y);
        s0.z = fmaf(d0.z, cwe0, s0.z); s0.w = fmaf(d0.w, cwe0, s0.w);
        s1.x = fmaf(d1.x, cwe1, s1.x); s1.y = fmaf(d1.y, cwe1, s1.y);
        s1.z = fmaf(d1.z, cwe1, s1.z); s1.w = fmaf(d1.w, cwe1, s1.w);
        *(float4*)&sp[w*2  ][j0] = s0;
        *(float4*)&sp[w*2+1][j0] = s1;
        m0 = fmaxf(m0, fmaxf(fmaxf(s0.x,s0.y), fmaxf(s0.z,s0.w)));
        m1 = fmaxf(m1, fmaxf(fmaxf(s1.x,s1.y), fmaxf(s1.z,s1.w)));
    }
    m0 = warpMax(m0); m1 = warpMax(m1);

    float sum0 = 0.f, sum1 = 0.f, sd0 = 0.f, sd1 = 0.f;
    #pragma unroll
    for(int cb=0;cb<4;cb++){
        int j0 = cb*128 + lane*4;
        float4 s0 = *(const float4*)&sp[w*2  ][j0];
        float4 s1 = *(const float4*)&sp[w*2+1][j0];
        float4 d0 = *(const float4*)(D0 + j0);
        float4 d1 = *(const float4*)(D1 + j0);
        float4 p0, p1;
        p0.x = __expf(s0.x-m0); p0.y = __expf(s0.y-m0); p0.z = __expf(s0.z-m0); p0.w = __expf(s0.w-m0);
        p1.x = __expf(s1.x-m1); p1.y = __expf(s1.y-m1); p1.z = __expf(s1.z-m1); p1.w = __expf(s1.w-m1);
        sum0 += (p0.x+p0.y)+(p0.z+p0.w);
        sum1 += (p1.x+p1.y)+(p1.z+p1.w);
        sd0 = fmaf(p0.x,d0.x,sd0); sd0 = fmaf(p0.y,d0.y,sd0); sd0 = fmaf(p0.z,d0.z,sd0); sd0 = fmaf(p0.w,d0.w,sd0);
        sd1 = fmaf(p1.x,d1.x,sd1); sd1 = fmaf(p1.y,d1.y,sd1); sd1 = fmaf(p1.z,d1.z,sd1); sd1 = fmaf(p1.w,d1.w,sd1);
        *(float4*)&sp[w*2  ][j0] = p0;
        *(float4*)&sp[w*2+1][j0] = p1;
    }
    sum0 = warpSum(sum0); sum1 = warpSum(sum1);
    sd0  = warpSum(sd0);  sd1  = warpSum(sd1);
    float inv0 = 1.f/sum0, inv1 = 1.f/sum1;
    __syncwarp();

    const float* Vp = v + bh*SN*HD;
    const float4* p0v = (const float4*)sp[w*2];
    const float4* p1v = (const float4*)sp[w*2+1];
    float a00=0.f,a01=0.f,a02=0.f,a03=0.f;
    float a10=0.f,a11=0.f,a12=0.f,a13=0.f;
    #pragma unroll 4
    for(int j4=0;j4<128;j4++){
        float4 p0 = p0v[j4];
        float4 p1 = p1v[j4];
        const float* vb = Vp + j4*128 + lane;
        float v0 = vb[0], v1 = vb[32], v2 = vb[64], v3 = vb[96];
        a00 = fmaf(p0.x,v0,a00); a01 = fmaf(p0.y,v1,a01);
        a02 = fmaf(p0.z,v2,a02); a03 = fmaf(p0.w,v3,a03);
        a10 = fmaf(p1.x,v0,a10); a11 = fmaf(p1.y,v1,a11);
        a12 = fmaf(p1.z,v2,a12); a13 = fmaf(p1.w,v3,a13);
    }
    float a0 = (a00+a01)+(a02+a03);
    float a1 = (a10+a11)+(a12+a13);
    float wl = We[h*32 + lane], bl = be[h*32 + lane];
    out[((b*SN + i0)*NH + h)*HD + lane] = tfround(a0*inv0 + (sd0*inv0)*wl + bl);
    out[((b*SN + i1)*NH + h)*HD + lane] = tfround(a1*inv1 + (sd1*inv1)*wl + bl);
}

// ---------------- fused gate + residual + next-layer LN stats ----------------
__global__ void __launch_bounds__(256) k_gate(const float* __restrict__ o, const float* __restrict__ wg,
                                              float* __restrict__ nodes,
                                              float* __restrict__ mu, float* __restrict__ rs){
    int w = threadIdx.x >> 5, lane = threadIdx.x & 31;
    int tok = blockIdx.x*8 + w;
    const float* op = o + tok*DIM;
    float* np = nodes + tok*DIM;
    float ov[8], nv[8];
    float s = 0.f;
    #pragma unroll
    for(int k=0;k<8;k++){
        int c = lane + k*32;
        ov[k] = op[c]; nv[k] = np[c];
        s = fmaf(ov[k], wg[c] + wg[512+c], s);
        s = fmaf(nv[k], wg[256+c] - wg[512+c], s);
    }
    s = warpSum(s);
    float g = 1.f / (1.f + __expf(-s));
    float vs = 0.f;
    float newv[8];
    #pragma unroll
    for(int k=0;k<8;k++){
        newv[k] = ov[k]*g + nv[k]*(1.f - g);
        vs += newv[k];
    }
    vs = warpSum(vs);
    float mean = vs * (1.f/DIM);
    float v2 = 0.f;
    #pragma unroll
    for(int k=0;k<8;k++){
        int c = lane + k*32;
        np[c] = newv[k];
        float d = newv[k] - mean;
        v2 = fmaf(d, d, v2);
    }
    v2 = warpSum(v2);
    if(lane == 0){ mu[tok] = mean; rs[tok] = rsqrtf(v2*(1.f/DIM) + 1e-5f); }
}

// ---------------- decoder ----------------
__global__ void __launch_bounds__(256) k_decode(const float* __restrict__ nodes, const float* __restrict__ Wd,
                                                float* __restrict__ out){
    int w = threadIdx.x >> 5, lane = threadIdx.x & 31;
    int tok = blockIdx.x*8 + w;
    const float* np = nodes + tok*DIM;
    float a0 = 0.f, a1 = 0.f, a2 = 0.f;
    #pragma unroll
    for(int k0=0;k0<8;k0++){
        int k = lane + k0*32;
        float nv = np[k];
        a0 = fmaf(nv, Wd[k*3+0], a0);
        a1 = fmaf(nv, Wd[k*3+1], a1);
        a2 = fmaf(nv, Wd[k*3+2], a2);
    }
    a0 = warpSum(a0); a1 = warpSum(a1); a2 = warpSum(a2);
    if(lane == 0){
        out[tok*3+0] = a0; out[tok*3+1] = a1; out[tok*3+2] = a2;
    }
}

// ---------------- launch ----------------
extern "C" void kernel_launch(void* const* d_in, const int* in_sizes, int n_in,
                              void* d_out, int out_size){
    (void)in_sizes; (void)n_in; (void)out_size;
    const float* x     = (const float*)d_in[0];
    const float* t     = (const float*)d_in[1];
    const float* W_enc = (const float*)d_in[2];
    const float* W_dec = (const float*)d_in[3];
    const float* ln_g  = (const float*)d_in[4];
    const float* ln_b  = (const float*)d_in[5];
    const float* Wq    = (const float*)d_in[6];
    const float* bq    = (const float*)d_in[7];
    const float* Wkv   = (const float*)d_in[8];
    const float* bkv   = (const float*)d_in[9];
    const float* We    = (const float*)d_in[10];
    const float* be    = (const float*)d_in[11];
    const float* Wo    = (const float*)d_in[12];
    const float* bo    = (const float*)d_in[13];
    const float* Wg    = (const float*)d_in[14];
    float* out = (float*)d_out;

    float *dist,*nodes,*mu,*rs,*h,*qkv,*q,*kt,*v,*qwe,*qbe,*attno,*ofull,*tab,*wq,*wkv,*wo;
    cudaGetSymbolAddress((void**)&dist,  g_dist);
    cudaGetSymbolAddress((void**)&nodes, g_nodes);
    cudaGetSymbolAddress((void**)&mu,    g_mu);
    cudaGetSymbolAddress((void**)&rs,    g_rs);
    cudaGetSymbolAddress((void**)&h,     g_h);
    cudaGetSymbolAddress((void**)&qkv,   g_qkv);
    cudaGetSymbolAddress((void**)&q,     g_q);
    cudaGetSymbolAddress((void**)&kt,    g_kt);
    cudaGetSymbolAddress((void**)&v,     g_v);
    cudaGetSymbolAddress((void**)&qwe,   g_qwe);
    cudaGetSymbolAddress((void**)&qbe,   g_qbe);
    cudaGetSymbolAddress((void**)&attno, g_attno);
    cudaGetSymbolAddress((void**)&ofull, g_out);
    cudaGetSymbolAddress((void**)&tab,   g_tab);
    cudaGetSymbolAddress((void**)&wq,    g_wq);
    cudaGetSymbolAddress((void**)&wkv,   g_wkv);
    cudaGetSymbolAddress((void**)&wo,    g_wo);

    k_tab   <<<32,256>>>(tab);
    k_cvtW  <<<2048,256>>>(Wq, Wkv, Wo, wq, wkv, wo);
    k_dist  <<<2048,256>>>(x, dist);
    k_encode<<<1024,256>>>(x, t, W_enc, nodes, mu, rs);

    for(int l=0;l<2;l++){
        k_ln<<<1024,256>>>(nodes, mu, rs, ln_g + l*DIM, ln_b + l*DIM, h);
        k_gemm_tc<true><<<dim3(12,8),256>>>(h, wq + l*DIM*DIM, bq + l*DIM,
                                            wkv + l*DIM*2*DIM, bkv + l*2*DIM, qkv);
        k_rot<<<1024,256>>>(qkv, We + l*DIM, be + l*DIM, tab, q, qwe, qbe, kt, v);
        k_attn2<<<512,256>>>(q, kt, v, qwe, qbe, dist, We + l*DIM, be + l*DIM, attno);
        k_gemm_tc<false><<<dim3(4,8),256>>>(attno, wo + l*DIM*DIM, bo + l*DIM,
                                            nullptr, nullptr, ofull);
        k_gate<<<128,256>>>(ofull, Wg + l*3*DIM, nodes, mu, rs);
    }
    k_decode<<<128,256>>>(nodes, W_dec, out);
}

// round 8
// speedup vs baseline: 1.2588x; 1.0176x over previous
#include <cuda_runtime.h>
#include <math.h>

#define NB 2
#define SN 512
#define DIM 256
#define NH 8
#define HD 32
#define QSCALE 0.17677669529663689f   // 1/sqrt(32)
#define FREQC  0.5756462732485115f    // ln(10000)/16

// ---------------- scratch (device globals) ----------------
__device__ __align__(256) float g_dist [NB*SN*SN];
__device__ __align__(256) float g_nodes[NB*SN*DIM];
__device__ __align__(256) float g_h    [NB*SN*DIM];      // LN'd, tf32-rounded
__device__ __align__(256) float g_qkv  [NB*SN*3*DIM];
__device__ __align__(256) float g_q    [NB*NH*SN*HD];
__device__ __align__(256) float g_kt   [NB*NH*HD*SN];
__device__ __align__(256) float g_v    [NB*NH*SN*HD];
__device__ __align__(256) float g_qwe  [NB*NH*SN];
__device__ __align__(256) float g_qbe  [NB*NH*SN];
__device__ __align__(256) float g_attno[NB*SN*DIM];      // tf32-rounded
__device__ __align__(256) float g_out  [NB*SN*DIM];
__device__ __align__(256) float g_tab  [SN*32];
__device__ __align__(256) float g_wq   [2*DIM*DIM];      // tf32-rounded weights
__device__ __align__(256) float g_wkv  [2*DIM*2*DIM];
__device__ __align__(256) float g_wo   [2*DIM*DIM];

// ---------------- helpers ----------------
__device__ __forceinline__ float warpSum(float v){
    #pragma unroll
    for(int o=16;o;o>>=1) v += __shfl_xor_sync(0xffffffffu, v, o);
    return v;
}
__device__ __forceinline__ float warpMax(float v){
    #pragma unroll
    for(int o=16;o;o>>=1) v = fmaxf(v, __shfl_xor_sync(0xffffffffu, v, o));
    return v;
}
__device__ __forceinline__ unsigned f2tf(float f){
    unsigned r; asm("cvt.rna.tf32.f32 %0, %1;" : "=r"(r) : "f"(f)); return r;
}
__device__ __forceinline__ float tfround(float f){ return __uint_as_float(f2tf(f)); }
__device__ __forceinline__ void mma8(float* c, unsigned a0, unsigned a1, unsigned a2, unsigned a3,
                                     unsigned b0, unsigned b1){
    asm("mma.sync.aligned.m16n8k8.row.col.f32.tf32.tf32.f32 "
        "{%0,%1,%2,%3},{%4,%5,%6,%7},{%8,%9},{%0,%1,%2,%3};"
        : "+f"(c[0]),"+f"(c[1]),"+f"(c[2]),"+f"(c[3])
        : "r"(a0),"r"(a1),"r"(a2),"r"(a3),"r"(b0),"r"(b1));
}
__device__ __forceinline__ void cpa16(unsigned s, const void* g){
    asm volatile("cp.async.cg.shared.global [%0], [%1], 16;" :: "r"(s), "l"(g));
}

// ---------------- prep: trig table + weight tf32-rounding (fused) ----------------
__global__ void __launch_bounds__(256) k_prep(const float* __restrict__ Wq, const float* __restrict__ Wkv,
                                              const float* __restrict__ Wo,
                                              float* __restrict__ wq, float* __restrict__ wkv,
                                              float* __restrict__ wo, float* __restrict__ tab){
    int i = blockIdx.x*256 + threadIdx.x;          // < 532480
    if(i < 8192){
        int ii = i >> 4, fd = i & 15;
        float fr = (float)ii * expf(-(float)fd * FREQC);
        tab[ii*32 + fd]      = cosf(fr);
        tab[ii*32 + 16 + fd] = sinf(fr);
    }
    int j = i - 8192;
    if(j >= 0){
        if(j < 131072)       wq[j]         = tfround(Wq[j]);
        else if(j < 393216)  wkv[j-131072] = tfround(Wkv[j-131072]);
        else if(j < 524288)  wo[j-393216]  = tfround(Wo[j-393216]);
    }
}

// ---------------- pairwise distances ----------------
__global__ void __launch_bounds__(256) k_dist(const float* __restrict__ x, float* __restrict__ dist){
    int idx = blockIdx.x*256 + threadIdx.x;
    int j = idx & 511; int rest = idx >> 9;
    int i = rest & 511; int b = rest >> 9;
    const float* xi = x + (b*SN + i)*3;
    const float* xj = x + (b*SN + j)*3;
    float d0 = xi[0]-xj[0], d1 = xi[1]-xj[1], d2 = xi[2]-xj[2];
    float q = d0*d0 + d1*d1 + d2*d2;
    dist[idx] = (q > 0.f) ? sqrtf(q) : 0.f;
}

// ---------------- encoder + fused LN (warp per token) ----------------
__global__ void __launch_bounds__(256) k_encode(const float* __restrict__ x, const float* __restrict__ t,
                                                const float* __restrict__ W,
                                                const float* __restrict__ lng, const float* __restrict__ lnb,
                                                float* __restrict__ nodes, float* __restrict__ h){
    int w = threadIdx.x >> 5, lane = threadIdx.x & 31;
    int tok = blockIdx.x*8 + w;
    const float* xp = x + tok*3;
    float x0 = xp[0], x1 = xp[1], x2 = xp[2], tt = t[tok];
    float v[8]; float s = 0.f;
    #pragma unroll
    for(int k=0;k<8;k++){
        int c = lane + k*32;
        v[k] = x0*W[c] + x1*W[256+c] + x2*W[512+c] + tt*W[768+c];
        s += v[k];
    }
    s = warpSum(s);
    float mean = s * (1.f/DIM);
    float v2 = 0.f;
    #pragma unroll
    for(int k=0;k<8;k++){ float d = v[k]-mean; v2 = fmaf(d,d,v2); }
    v2 = warpSum(v2);
    float rstd = rsqrtf(v2*(1.f/DIM) + 1e-5f);
    #pragma unroll
    for(int k=0;k<8;k++){
        int c = lane + k*32;
        int idx = tok*DIM + c;
        nodes[idx] = v[k];
        h[idx] = tfround(fmaf((v[k]-mean)*rstd, lng[c], lnb[c]));
    }
}

// ============ tf32 tensor-core GEMM, cp.async 3-stage: BM=128, BN=64, BK=16 ============
template<bool QKV>
__global__ void __launch_bounds__(256) k_gemm_tc(const float* __restrict__ A,
        const float* __restrict__ W1, const float* __restrict__ b1,
        const float* __restrict__ W2, const float* __restrict__ b2,
        float* __restrict__ C){
    constexpr int BM=128, BK=16, BN=64, K=256, NST=3;
    constexpr int LDC = QKV ? 768 : 256;
    constexpr int ASZ = BM*(BK+4), BSZ = BK*(BN+8);
    __shared__ __align__(16) float As[NST][BM][BK+4];
    __shared__ __align__(16) float Bs[NST][BK][BN+8];
    int tx = threadIdx.x;
    int wid = tx>>5, lane = tx&31;
    int bcol = blockIdx.x*BN, brow = blockIdx.y*BM;

    const float* W; const float* bias; int ldb;
    if(QKV){
        if(bcol < 256){ W = W1 + bcol;        bias = b1 + bcol;        ldb = 256; }
        else          { W = W2 + (bcol-256);  bias = b2 + (bcol-256);  ldb = 512; }
    } else {            W = W1 + bcol;        bias = b1 + bcol;        ldb = 256; }

    int ar[2], akk[2];
    #pragma unroll
    for(int u=0;u<2;u++){ int f = tx + u*256; ar[u]=f>>2; akk[u]=(f&3)*4; }
    int bkr = tx>>4, bkc = (tx&15)*4;

    const float* Ab = A + brow*K;
    unsigned sA = (unsigned)__cvta_generic_to_shared(&As[0][0][0]);
    unsigned sB = (unsigned)__cvta_generic_to_shared(&Bs[0][0][0]);
    unsigned sa0 = sA + (ar[0]*(BK+4) + akk[0])*4u;
    unsigned sa1 = sA + (ar[1]*(BK+4) + akk[1])*4u;
    unsigned sb0 = sB + (bkr*(BN+8) + bkc)*4u;
    const float* ga0 = Ab + ar[0]*K + akk[0];
    const float* ga1 = Ab + ar[1]*K + akk[1];
    const float* gb0 = W + bkr*ldb + bkc;

    const int NT = K/BK;   // 16
    #pragma unroll
    for(int s=0;s<NST;s++){
        cpa16(sa0 + s*ASZ*4u, ga0 + s*BK);
        cpa16(sa1 + s*ASZ*4u, ga1 + s*BK);
        cpa16(sb0 + s*BSZ*4u, gb0 + s*BK*ldb);
        asm volatile("cp.async.commit_group;" ::: "memory");
    }

    int wm = (wid & 3)*32, wn = (wid >> 2)*32;
    float acc[2][4][4];
    #pragma unroll
    for(int mt=0;mt<2;mt++)
        #pragma unroll
        for(int nt=0;nt<4;nt++)
            #pragma unroll
            for(int e=0;e<4;e++) acc[mt][nt][e] = 0.f;

    for(int t=0;t<NT;t++){
        asm volatile("cp.async.wait_group 2;" ::: "memory");
        __syncthreads();
        int buf = t % NST;
        #pragma unroll
        for(int ks=0;ks<2;ks++){
            int kq = ks*8 + (lane&3);
            unsigned a[2][4], b[4][2];
            int arow = wm + (lane>>2);
            #pragma unroll
            for(int mt=0;mt<2;mt++){
                int r = arow + mt*16;
                a[mt][0] = __float_as_uint(As[buf][r  ][kq]);
                a[mt][1] = __float_as_uint(As[buf][r+8][kq]);
                a[mt][2] = __float_as_uint(As[buf][r  ][kq+4]);
                a[mt][3] = __float_as_uint(As[buf][r+8][kq+4]);
            }
            int bc0 = wn + (lane>>2);
            #pragma unroll
            for(int nt=0;nt<4;nt++){
                b[nt][0] = __float_as_uint(Bs[buf][kq  ][bc0 + nt*8]);
                b[nt][1] = __float_as_uint(Bs[buf][kq+4][bc0 + nt*8]);
            }
            #pragma unroll
            for(int mt=0;mt<2;mt++)
                #pragma unroll
                for(int nt=0;nt<4;nt++)
                    mma8(acc[mt][nt], a[mt][0],a[mt][1],a[mt][2],a[mt][3], b[nt][0],b[nt][1]);
        }
        __syncthreads();
        int nt_ = t + NST;
        if(nt_ < NT){
            cpa16(sa0 + buf*ASZ*4u, ga0 + nt_*BK);
            cpa16(sa1 + buf*ASZ*4u, ga1 + nt_*BK);
            cpa16(sb0 + buf*BSZ*4u, gb0 + nt_*BK*ldb);
        }
        asm volatile("cp.async.commit_group;" ::: "memory");
    }

    #pragma unroll
    for(int mt=0;mt<2;mt++){
        int r = brow + wm + mt*16 + (lane>>2);
        #pragma unroll
        for(int nt=0;nt<4;nt++){
            int lc = wn + nt*8 + (lane&3)*2;
            float bz0 = bias[lc], bz1 = bias[lc+1];
            float* c0p = C + r*LDC + bcol + lc;
            c0p[0] = acc[mt][nt][0] + bz0;
            c0p[1] = acc[mt][nt][1] + bz1;
            float* c1p = C + (r+8)*LDC + bcol + lc;
            c1p[0] = acc[mt][nt][2] + bz0;
            c1p[1] = acc[mt][nt][3] + bz1;
        }
    }
}

// ---------------- rotary Q/K (+ q.We, q.be) + V relayout (table trig) ----------------
__global__ void __launch_bounds__(256) k_rot(const float* __restrict__ qkv,
                                             const float* __restrict__ We, const float* __restrict__ be,
                                             const float* __restrict__ tab,
                                             float* __restrict__ q, float* __restrict__ qwe, float* __restrict__ qbe,
                                             float* __restrict__ kt, float* __restrict__ v){
    int bi = blockIdx.x;
    int b = bi >> 9, i = bi & 511;
    int h = threadIdx.x >> 5, d = threadIdx.x & 31;
    int bh = b*NH + h;
    const float* row = qkv + bi*768;
    int fd = d & 15;
    float cs = tab[i*32 + fd];
    float sn = tab[i*32 + 16 + fd];

    float qv = row[h*32 + d];
    float qo = row[h*32 + ((d+16)&31)];
    float qrot = (d < 16) ? -qo : qo;
    float qval = (qv*cs + qrot*sn) * QSCALE;
    q[(bh*SN + i)*HD + d] = qval;

    float kv = row[256 + h*32 + d];
    float ko = row[256 + h*32 + ((d+16)&31)];
    float krot = (d < 16) ? -ko : ko;
    kt[(bh*HD + d)*SN + i] = kv*cs + krot*sn;

    v[(bh*SN + i)*HD + d] = row[512 + h*32 + d];

    float dwe = warpSum(qval * We[h*32 + d]);
    float dbe = warpSum(qval * be[h*32 + d]);
    if(d == 0){ qwe[bh*SN + i] = dwe; qbe[bh*SN + i] = dbe; }
}

// ---------------- attention: warp handles 2 query rows ----------------
__global__ void __launch_bounds__(256) k_attn2(
    const float* __restrict__ q, const float* __restrict__ kt, const float* __restrict__ v,
    const float* __restrict__ qwe, const float* __restrict__ qbe, const float* __restrict__ dist,
    const float* __restrict__ We, const float* __restrict__ be, float* __restrict__ out)
{
    __shared__ __align__(16) float sp[16][512];
    int w = threadIdx.x >> 5, lane = threadIdx.x & 31;
    int bh = blockIdx.x >> 5;
    int chunk = blockIdx.x & 31;
    int b = bh >> 3, h = bh & 7;
    int i0 = chunk*16 + w*2, i1 = i0 + 1;

    float qr0[32], qr1[32];
    {
        float qv0 = q[(bh*SN + i0)*HD + lane];
        float qv1 = q[(bh*SN + i1)*HD + lane];
        #pragma unroll
        for(int d=0;d<32;d++){ qr0[d] = __shfl_sync(0xffffffffu, qv0, d);
                               qr1[d] = __shfl_sync(0xffffffffu, qv1, d); }
    }
    float cwe0 = qwe[bh*SN + i0], cwe1 = qwe[bh*SN + i1];
    float cbe0 = qbe[bh*SN + i0], cbe1 = qbe[bh*SN + i1];
    const float* Kt = kt + bh*HD*SN;
    const float* D0 = dist + (b*SN + i0)*SN;
    const float* D1 = dist + (b*SN + i1)*SN;

    float m0 = -1e30f, m1 = -1e30f;
    #pragma unroll
    for(int cb=0;cb<4;cb++){
        int j0 = cb*128 + lane*4;
        float4 s0 = make_float4(cbe0,cbe0,cbe0,cbe0);
        float4 s1 = make_float4(cbe1,cbe1,cbe1,cbe1);
        #pragma unroll
        for(int d=0;d<32;d++){
            float4 kk = *(const float4*)(Kt + d*SN + j0);
            s0.x = fmaf(qr0[d], kk.x, s0.x); s0.y = fmaf(qr0[d], kk.y, s0.y);
            s0.z = fmaf(qr0[d], kk.z, s0.z); s0.w = fmaf(qr0[d], kk.w, s0.w);
            s1.x = fmaf(qr1[d], kk.x, s1.x); s1.y = fmaf(qr1[d], kk.y, s1.y);
            s1.z = fmaf(qr1[d], kk.z, s1.z); s1.w = fmaf(qr1[d], kk.w, s1.w);
        }
        float4 d0 = *(const float4*)(D0 + j0);
        float4 d1 = *(const float4*)(D1 + j0);
        s0.x = fmaf(d0.x, cwe0, s0.x); s0.y = fmaf(d0.y, cwe0, s0.y);
        s0.z = fmaf(d0.z, cwe0, s0.z); s0.w = fmaf(d0.w, cwe0, s0.w);
        s1.x = fmaf(d1.x, cwe1, s1.x); s1.y = fmaf(d1.y, cwe1, s1.y);
        s1.z = fmaf(d1.z, cwe1, s1.z); s1.w = fmaf(d1.w, cwe1, s1.w);
        *(float4*)&sp[w*2  ][j0] = s0;
        *(float4*)&sp[w*2+1][j0] = s1;
        m0 = fmaxf(m0, fmaxf(fmaxf(s0.x,s0.y), fmaxf(s0.z,s0.w)));
        m1 = fmaxf(m1, fmaxf(fmaxf(s1.x,s1.y), fmaxf(s1.z,s1.w)));
    }
    m0 = warpMax(m0); m1 = warpMax(m1);

    float sum0 = 0.f, sum1 = 0.f, sd0 = 0.f, sd1 = 0.f;
    #pragma unroll
    for(int cb=0;cb<4;cb++){
        int j0 = cb*128 + lane*4;
        float4 s0 = *(const float4*)&sp[w*2  ][j0];
        float4 s1 = *(const float4*)&sp[w*2+1][j0];
        float4 d0 = *(const float4*)(D0 + j0);
        float4 d1 = *(const float4*)(D1 + j0);
        float4 p0, p1;
        p0.x = __expf(s0.x-m0); p0.y = __expf(s0.y-m0); p0.z = __expf(s0.z-m0); p0.w = __expf(s0.w-m0);
        p1.x = __expf(s1.x-m1); p1.y = __expf(s1.y-m1); p1.z = __expf(s1.z-m1); p1.w = __expf(s1.w-m1);
        sum0 += (p0.x+p0.y)+(p0.z+p0.w);
        sum1 += (p1.x+p1.y)+(p1.z+p1.w);
        sd0 = fmaf(p0.x,d0.x,sd0); sd0 = fmaf(p0.y,d0.y,sd0); sd0 = fmaf(p0.z,d0.z,sd0); sd0 = fmaf(p0.w,d0.w,sd0);
        sd1 = fmaf(p1.x,d1.x,sd1); sd1 = fmaf(p1.y,d1.y,sd1); sd1 = fmaf(p1.z,d1.z,sd1); sd1 = fmaf(p1.w,d1.w,sd1);
        *(float4*)&sp[w*2  ][j0] = p0;
        *(float4*)&sp[w*2+1][j0] = p1;
    }
    sum0 = warpSum(sum0); sum1 = warpSum(sum1);
    sd0  = warpSum(sd0);  sd1  = warpSum(sd1);
    float inv0 = 1.f/sum0, inv1 = 1.f/sum1;
    __syncwarp();

    const float* Vp = v + bh*SN*HD;
    const float4* p0v = (const float4*)sp[w*2];
    const float4* p1v = (const float4*)sp[w*2+1];
    float a00=0.f,a01=0.f,a02=0.f,a03=0.f;
    float a10=0.f,a11=0.f,a12=0.f,a13=0.f;
    #pragma unroll 4
    for(int j4=0;j4<128;j4++){
        float4 p0 = p0v[j4];
        float4 p1 = p1v[j4];
        const float* vb = Vp + j4*128 + lane;
        float v0 = vb[0], v1 = vb[32], v2 = vb[64], v3 = vb[96];
        a00 = fmaf(p0.x,v0,a00); a01 = fmaf(p0.y,v1,a01);
        a02 = fmaf(p0.z,v2,a02); a03 = fmaf(p0.w,v3,a03);
        a10 = fmaf(p1.x,v0,a10); a11 = fmaf(p1.y,v1,a11);
        a12 = fmaf(p1.z,v2,a12); a13 = fmaf(p1.w,v3,a13);
    }
    float a0 = (a00+a01)+(a02+a03);
    float a1 = (a10+a11)+(a12+a13);
    float wl = We[h*32 + lane], bl = be[h*32 + lane];
    out[((b*SN + i0)*NH + h)*HD + lane] = tfround(a0*inv0 + (sd0*inv0)*wl + bl);
    out[((b*SN + i1)*NH + h)*HD + lane] = tfround(a1*inv1 + (sd1*inv1)*wl + bl);
}

// ---------------- gate + residual, fused next-LN (l=0) or fused decode (l=1) ----------------
template<bool LAST>
__global__ void __launch_bounds__(256) k_gate(const float* __restrict__ o, const float* __restrict__ wg,
                                              float* __restrict__ nodes,
                                              const float* __restrict__ lng, const float* __restrict__ lnb,
                                              float* __restrict__ h,
                                              const float* __restrict__ Wd, float* __restrict__ out){
    int w = threadIdx.x >> 5, lane = threadIdx.x & 31;
    int tok = blockIdx.x*8 + w;
    const float* op = o + tok*DIM;
    float* np = nodes + tok*DIM;
    float ov[8], nv[8];
    float s = 0.f;
    #pragma unroll
    for(int k=0;k<8;k++){
        int c = lane + k*32;
        ov[k] = op[c]; nv[k] = np[c];
        s = fmaf(ov[k], wg[c] + wg[512+c], s);
        s = fmaf(nv[k], wg[256+c] - wg[512+c], s);
    }
    s = warpSum(s);
    float g = 1.f / (1.f + __expf(-s));
    float newv[8];
    float vs = 0.f;
    #pragma unroll
    for(int k=0;k<8;k++){
        newv[k] = ov[k]*g + nv[k]*(1.f - g);
        vs += newv[k];
    }
    if(!LAST){
        vs = warpSum(vs);
        float mean = vs * (1.f/DIM);
        float v2 = 0.f;
        #pragma unroll
        for(int k=0;k<8;k++){ float d = newv[k]-mean; v2 = fmaf(d,d,v2); }
        v2 = warpSum(v2);
        float rstd = rsqrtf(v2*(1.f/DIM) + 1e-5f);
        #pragma unroll
        for(int k=0;k<8;k++){
            int c = lane + k*32;
            np[c] = newv[k];
            h[tok*DIM + c] = tfround(fmaf((newv[k]-mean)*rstd, lng[c], lnb[c]));
        }
    } else {
        float a0 = 0.f, a1 = 0.f, a2 = 0.f;
        #pragma unroll
        for(int k=0;k<8;k++){
            int c = lane + k*32;
            a0 = fmaf(newv[k], Wd[c*3+0], a0);
            a1 = fmaf(newv[k], Wd[c*3+1], a1);
            a2 = fmaf(newv[k], Wd[c*3+2], a2);
        }
        a0 = warpSum(a0); a1 = warpSum(a1); a2 = warpSum(a2);
        if(lane == 0){
            out[tok*3+0] = a0; out[tok*3+1] = a1; out[tok*3+2] = a2;
        }
    }
}

// ---------------- launch ----------------
extern "C" void kernel_launch(void* const* d_in, const int* in_sizes, int n_in,
                              void* d_out, int out_size){
    (void)in_sizes; (void)n_in; (void)out_size;
    const float* x     = (const float*)d_in[0];
    const float* t     = (const float*)d_in[1];
    const float* W_enc = (const float*)d_in[2];
    const float* W_dec = (const float*)d_in[3];
    const float* ln_g  = (const float*)d_in[4];
    const float* ln_b  = (const float*)d_in[5];
    const float* Wq    = (const float*)d_in[6];
    const float* bq    = (const float*)d_in[7];
    const float* Wkv   = (const float*)d_in[8];
    const float* bkv   = (const float*)d_in[9];
    const float* We    = (const float*)d_in[10];
    const float* be    = (const float*)d_in[11];
    const float* Wo    = (const float*)d_in[12];
    const float* bo    = (const float*)d_in[13];
    const float* Wg    = (const float*)d_in[14];
    float* out = (float*)d_out;

    float *dist,*nodes,*h,*qkv,*q,*kt,*v,*qwe,*qbe,*attno,*ofull,*tab,*wq,*wkv,*wo;
    cudaGetSymbolAddress((void**)&dist,  g_dist);
    cudaGetSymbolAddress((void**)&nodes, g_nodes);
    cudaGetSymbolAddress((void**)&h,     g_h);
    cudaGetSymbolAddress((void**)&qkv,   g_qkv);
    cudaGetSymbolAddress((void**)&q,     g_q);
    cudaGetSymbolAddress((void**)&kt,    g_kt);
    cudaGetSymbolAddress((void**)&v,     g_v);
    cudaGetSymbolAddress((void**)&qwe,   g_qwe);
    cudaGetSymbolAddress((void**)&qbe,   g_qbe);
    cudaGetSymbolAddress((void**)&attno, g_attno);
    cudaGetSymbolAddress((void**)&ofull, g_out);
    cudaGetSymbolAddress((void**)&tab,   g_tab);
    cudaGetSymbolAddress((void**)&wq,    g_wq);
    cudaGetSymbolAddress((void**)&wkv,   g_wkv);
    cudaGetSymbolAddress((void**)&wo,    g_wo);

    // fork: dist on a side stream, join before first attention
    cudaStream_t sB;
    cudaStreamCreateWithFlags(&sB, cudaStreamNonBlocking);
    cudaEvent_t eF, eJ;
    cudaEventCreateWithFlags(&eF, cudaEventDisableTiming);
    cudaEventCreateWithFlags(&eJ, cudaEventDisableTiming);
    cudaEventRecord(eF, 0);
    cudaStreamWaitEvent(sB, eF, 0);
    k_dist<<<2048,256,0,sB>>>(x, dist);
    cudaEventRecord(eJ, sB);

    k_prep  <<<2080,256>>>(Wq, Wkv, Wo, wq, wkv, wo, tab);
    k_encode<<<128,256>>>(x, t, W_enc, ln_g, ln_b, nodes, h);

    for(int l=0;l<2;l++){
        k_gemm_tc<true><<<dim3(12,8),256>>>(h, wq + l*DIM*DIM, bq + l*DIM,
                                            wkv + l*DIM*2*DIM, bkv + l*2*DIM, qkv);
        k_rot<<<1024,256>>>(qkv, We + l*DIM, be + l*DIM, tab, q, qwe, qbe, kt, v);
        if(l == 0) cudaStreamWaitEvent(0, eJ, 0);
        k_attn2<<<512,256>>>(q, kt, v, qwe, qbe, dist, We + l*DIM, be + l*DIM, attno);
        k_gemm_tc<false><<<dim3(4,8),256>>>(attno, wo + l*DIM*DIM, bo + l*DIM,
                                            nullptr, nullptr, ofull);
        if(l == 0)
            k_gate<false><<<128,256>>>(ofull, Wg, nodes, ln_g + DIM, ln_b + DIM, h,
                                       nullptr, nullptr);
        else
            k_gate<true><<<128,256>>>(ofull, Wg + 3*DIM, nodes, nullptr, nullptr, nullptr,
                                      W_dec, out);
    }
    // streams/events intentionally not destroyed mid-capture (kernel_launch is
    // invoked only for the correctness run and the single graph capture)
}